// round 1
// baseline (speedup 1.0000x reference)
#include <cuda_runtime.h>
#include <cuda_bf16.h>

// ---------------------------------------------------------------------------
// TFConvBertSelfAttention  (B=4, S=2048, C=768, H=6, D=64, AHS=384, K=9)
//
// Pipeline:
//   q  = hs @ Wq + bq          (SGEMM 8192x384x768)
//   k  = hs @ Wk + bk
//   v  = hs @ Wv + bv
//   co = hs @ Wco + bco
//   dw = depthwise_conv9(hs)   (elementwise, SAME pad)
//   kc = dw @ pw + conv_bias   (SGEMM)
//   ck = softmax_K( (kc*q) @ Wck + bck )     [8192, H, 9]
//   out[:, :,384:768] = sum_t ck[...,t] * co_shifted(t)    (dynamic conv)
//   out[:, :,  0:384] = flash_attention(q,k,v) * head_mask
// ---------------------------------------------------------------------------

#define BATCH   4
#define SEQ     2048
#define CIN     768
#define NHEAD   6
#define HDIM    64
#define AHS     384
#define KTAPS   9
#define MROWS   (BATCH * SEQ)          // 8192

// ------------------------- scratch (static device mem) ---------------------
__device__ float g_q [MROWS * AHS];
__device__ float g_k [MROWS * AHS];
__device__ float g_v [MROWS * AHS];
__device__ float g_co[MROWS * AHS];
__device__ float g_kc[MROWS * AHS];
__device__ float g_dw[MROWS * CIN];
__device__ float g_ck[MROWS * NHEAD * KTAPS];

// ------------------------- SGEMM: C = A[MxK] @ B[KxN] + bias ---------------
// Tile 64x64, Kstep 16, 256 threads, 4x4 microtile per thread.
__global__ __launch_bounds__(256)
void sgemm_bias(const float* __restrict__ A, const float* __restrict__ B,
                const float* __restrict__ bias, float* __restrict__ C,
                int M, int N, int K)
{
    __shared__ float As[16][65];   // transposed, padded
    __shared__ float Bs[16][64];

    const int tid = threadIdx.x;
    const int tx = tid & 15;
    const int ty = tid >> 4;
    const int m0 = blockIdx.y * 64;
    const int n0 = blockIdx.x * 64;

    float acc[4][4];
#pragma unroll
    for (int i = 0; i < 4; i++)
#pragma unroll
        for (int j = 0; j < 4; j++) acc[i][j] = 0.f;

    const int a_row = tid >> 2;            // 0..63
    const int a_k4  = (tid & 3) * 4;       // 0,4,8,12
    const int b_row = tid >> 4;            // 0..15
    const int b_c4  = (tid & 15) * 4;      // 0..60

    const float* Aptr = A + (size_t)(m0 + a_row) * K + a_k4;
    const float* Bptr = B + (size_t)b_row * N + n0 + b_c4;

    for (int k0 = 0; k0 < K; k0 += 16) {
        float4 av = *(const float4*)(Aptr + k0);
        As[a_k4 + 0][a_row] = av.x;
        As[a_k4 + 1][a_row] = av.y;
        As[a_k4 + 2][a_row] = av.z;
        As[a_k4 + 3][a_row] = av.w;
        *(float4*)&Bs[b_row][b_c4] = *(const float4*)(Bptr + (size_t)k0 * N);
        __syncthreads();

#pragma unroll
        for (int kk = 0; kk < 16; kk++) {
            float ar[4], br[4];
#pragma unroll
            for (int i = 0; i < 4; i++) ar[i] = As[kk][ty + i * 16];
#pragma unroll
            for (int j = 0; j < 4; j++) br[j] = Bs[kk][tx + j * 16];
#pragma unroll
            for (int i = 0; i < 4; i++)
#pragma unroll
                for (int j = 0; j < 4; j++) acc[i][j] += ar[i] * br[j];
        }
        __syncthreads();
    }

#pragma unroll
    for (int j = 0; j < 4; j++) {
        const int col = n0 + tx + j * 16;
        const float bv = bias[col];
#pragma unroll
        for (int i = 0; i < 4; i++) {
            const int row = m0 + ty + i * 16;
            C[(size_t)row * N + col] = acc[i][j] + bv;
        }
    }
}

// ------------------------- depthwise conv (K=9, SAME) ----------------------
__global__ void dwconv9(const float* __restrict__ hs, const float* __restrict__ w,
                        float* __restrict__ out)
{
    int idx = blockIdx.x * blockDim.x + threadIdx.x;
    if (idx >= MROWS * CIN) return;
    int c = idx % CIN;
    int s = (idx / CIN) & (SEQ - 1);
    int b = idx / (CIN * SEQ);
    float acc = 0.f;
#pragma unroll
    for (int t = 0; t < KTAPS; t++) {
        int ss = s + t - 4;
        if (ss >= 0 && ss < SEQ)
            acc += hs[((size_t)(b * SEQ + ss)) * CIN + c] * w[t * CIN + c];
    }
    out[idx] = acc;
}

// ---------------- span kernel: ck = softmax_K((kc*q) @ Wck + bck) ----------
__global__ __launch_bounds__(128)
void span_kernel(const float* __restrict__ kc, const float* __restrict__ q,
                 const float* __restrict__ Wck, const float* __restrict__ bck,
                 float* __restrict__ ck)
{
    const int row = blockIdx.x;            // 0..8191
    __shared__ float a[AHS];
    __shared__ float sv[NHEAD * KTAPS];
    const int tid = threadIdx.x;

    for (int c = tid; c < AHS; c += 128)
        a[c] = kc[(size_t)row * AHS + c] * q[(size_t)row * AHS + c];
    __syncthreads();

    if (tid < NHEAD * KTAPS) {
        float acc = bck[tid];
#pragma unroll 4
        for (int c = 0; c < AHS; c++)
            acc += a[c] * Wck[c * (NHEAD * KTAPS) + tid];
        sv[tid] = acc;
    }
    __syncthreads();

    if (tid < NHEAD) {
        float m = -1e30f;
#pragma unroll
        for (int t = 0; t < KTAPS; t++) m = fmaxf(m, sv[tid * KTAPS + t]);
        float e[KTAPS]; float s = 0.f;
#pragma unroll
        for (int t = 0; t < KTAPS; t++) { e[t] = __expf(sv[tid * KTAPS + t] - m); s += e[t]; }
        const float inv = 1.f / s;
#pragma unroll
        for (int t = 0; t < KTAPS; t++)
            ck[(size_t)row * (NHEAD * KTAPS) + tid * KTAPS + t] = e[t] * inv;
    }
}

// ---------------- dynamic conv gather -> out[:, 384:768] -------------------
__global__ void dynconv(const float* __restrict__ ck, const float* __restrict__ co,
                        float* __restrict__ out)
{
    int idx = blockIdx.x * blockDim.x + threadIdx.x;
    if (idx >= MROWS * AHS) return;
    const int hd  = idx % AHS;
    const int row = idx / AHS;
    const int b = row >> 11;
    const int s = row & (SEQ - 1);
    const int h = hd >> 6;
    const float* ckr = ck + (size_t)row * (NHEAD * KTAPS) + h * KTAPS;
    float acc = 0.f;
#pragma unroll
    for (int t = 0; t < KTAPS; t++) {
        int ss = s + t - 4;
        float cv = (ss >= 0 && ss < SEQ) ? co[((size_t)(b * SEQ + ss)) * AHS + hd] : 0.f;
        acc = fmaf(ckr[t], cv, acc);
    }
    out[(size_t)row * (2 * AHS) + AHS + hd] = acc;
}

// ---------------- flash attention -> out[:, 0:384] -------------------------
// grid: (SEQ/128, BATCH*NHEAD). 128 threads; thread t owns query row q0+t.
#define BQ 128
#define BK 32
__global__ __launch_bounds__(BQ)
void attn(const float* __restrict__ q, const float* __restrict__ k,
          const float* __restrict__ v, const float* __restrict__ mask,
          const float* __restrict__ headmask, float* __restrict__ out)
{
    const int bh = blockIdx.y;
    const int b = bh / NHEAD, h = bh % NHEAD;
    const int qrow = blockIdx.x * BQ + threadIdx.x;

    const float* qp = q + ((size_t)(b * SEQ + qrow)) * AHS + h * HDIM;
    float qr[HDIM];
#pragma unroll
    for (int d = 0; d < HDIM; d++) qr[d] = qp[d] * 0.125f;   // 1/sqrt(64)

    float acc[HDIM];
#pragma unroll
    for (int d = 0; d < HDIM; d++) acc[d] = 0.f;
    float mrun = -1e30f, l = 0.f;

    __shared__ float Ks[BK][HDIM];
    __shared__ float Vs[BK][HDIM];

    const float* kbase = k + ((size_t)b * SEQ) * AHS + h * HDIM;
    const float* vbase = v + ((size_t)b * SEQ) * AHS + h * HDIM;
    const float* mbase = mask + (size_t)b * SEQ;

    for (int kb = 0; kb < SEQ; kb += BK) {
        __syncthreads();
        // cooperative coalesced load: 32 rows x 64 floats
        for (int i = threadIdx.x; i < BK * HDIM; i += BQ) {
            const int j = i >> 6, d = i & 63;
            Ks[j][d] = kbase[(size_t)(kb + j) * AHS + d];
            Vs[j][d] = vbase[(size_t)(kb + j) * AHS + d];
        }
        __syncthreads();

        float s[BK];
        float tmax = -1e30f;
#pragma unroll
        for (int j = 0; j < BK; j++) {
            float dot = 0.f;
            const float4* kr = (const float4*)&Ks[j][0];
#pragma unroll
            for (int d4 = 0; d4 < HDIM / 4; d4++) {
                float4 kv = kr[d4];
                dot = fmaf(qr[d4 * 4 + 0], kv.x, dot);
                dot = fmaf(qr[d4 * 4 + 1], kv.y, dot);
                dot = fmaf(qr[d4 * 4 + 2], kv.z, dot);
                dot = fmaf(qr[d4 * 4 + 3], kv.w, dot);
            }
            dot += mbase[kb + j];
            s[j] = dot;
            tmax = fmaxf(tmax, dot);
        }

        const float newm = fmaxf(mrun, tmax);
        const float corr = __expf(mrun - newm);
        l *= corr;
#pragma unroll
        for (int d = 0; d < HDIM; d++) acc[d] *= corr;

#pragma unroll
        for (int j = 0; j < BK; j++) {
            const float p = __expf(s[j] - newm);
            l += p;
            const float4* vr = (const float4*)&Vs[j][0];
#pragma unroll
            for (int d4 = 0; d4 < HDIM / 4; d4++) {
                float4 vv = vr[d4];
                acc[d4 * 4 + 0] = fmaf(p, vv.x, acc[d4 * 4 + 0]);
                acc[d4 * 4 + 1] = fmaf(p, vv.y, acc[d4 * 4 + 1]);
                acc[d4 * 4 + 2] = fmaf(p, vv.z, acc[d4 * 4 + 2]);
                acc[d4 * 4 + 3] = fmaf(p, vv.w, acc[d4 * 4 + 3]);
            }
        }
        mrun = newm;
    }

    const float inv = headmask[h] / l;
    float* op = out + ((size_t)(b * SEQ + qrow)) * (2 * AHS) + h * HDIM;
#pragma unroll
    for (int d = 0; d < HDIM; d++) op[d] = acc[d] * inv;
}

// ---------------------------------------------------------------------------
extern "C" void kernel_launch(void* const* d_in, const int* in_sizes, int n_in,
                              void* d_out, int out_size)
{
    const float* hs    = (const float*)d_in[0];
    const float* amask = (const float*)d_in[1];
    const float* hmask = (const float*)d_in[2];
    const float* Wq    = (const float*)d_in[3];
    const float* bq    = (const float*)d_in[4];
    const float* Wk    = (const float*)d_in[5];
    const float* bk    = (const float*)d_in[6];
    const float* Wv    = (const float*)d_in[7];
    const float* bv    = (const float*)d_in[8];
    const float* dwk   = (const float*)d_in[9];
    const float* pw    = (const float*)d_in[10];
    const float* cb    = (const float*)d_in[11];
    const float* Wck   = (const float*)d_in[12];
    const float* bck   = (const float*)d_in[13];
    const float* Wco   = (const float*)d_in[14];
    const float* bco   = (const float*)d_in[15];
    float* out = (float*)d_out;

    float *pq, *pk, *pv, *pco, *pkc, *pdw, *pck;
    cudaGetSymbolAddress((void**)&pq,  g_q);
    cudaGetSymbolAddress((void**)&pk,  g_k);
    cudaGetSymbolAddress((void**)&pv,  g_v);
    cudaGetSymbolAddress((void**)&pco, g_co);
    cudaGetSymbolAddress((void**)&pkc, g_kc);
    cudaGetSymbolAddress((void**)&pdw, g_dw);
    cudaGetSymbolAddress((void**)&pck, g_ck);

    dim3 ggrid(AHS / 64, MROWS / 64);   // (6, 128)
    sgemm_bias<<<ggrid, 256>>>(hs, Wq,  bq,  pq,  MROWS, AHS, CIN);
    sgemm_bias<<<ggrid, 256>>>(hs, Wk,  bk,  pk,  MROWS, AHS, CIN);
    sgemm_bias<<<ggrid, 256>>>(hs, Wv,  bv,  pv,  MROWS, AHS, CIN);
    sgemm_bias<<<ggrid, 256>>>(hs, Wco, bco, pco, MROWS, AHS, CIN);

    {
        int n = MROWS * CIN;
        dwconv9<<<(n + 255) / 256, 256>>>(hs, dwk, pdw);
    }
    sgemm_bias<<<ggrid, 256>>>(pdw, pw, cb, pkc, MROWS, AHS, CIN);

    span_kernel<<<MROWS, 128>>>(pkc, pq, Wck, bck, pck);

    {
        int n = MROWS * AHS;
        dynconv<<<(n + 255) / 256, 256>>>(pck, pco, out);
    }

    dim3 agrid(SEQ / BQ, BATCH * NHEAD);   // (16, 24)
    attn<<<agrid, BQ>>>(pq, pk, pv, amask, hmask, out);
}

// round 2
// speedup vs baseline: 2.2701x; 2.2701x over previous
#include <cuda_runtime.h>
#include <cuda_bf16.h>

// ---------------------------------------------------------------------------
// TFConvBertSelfAttention  (B=4, S=2048, C=768, H=6, D=64, AHS=384, K=9)
// R2: all GEMM-shaped work on tensor cores via mma.sync m16n8k8 tf32 (RNA cvt).
// ---------------------------------------------------------------------------

#define BATCH   4
#define SEQ     2048
#define CIN     768
#define NHEAD   6
#define HDIM    64
#define AHS     384
#define KTAPS   9
#define MROWS   (BATCH * SEQ)          // 8192

// ------------------------- scratch (static device mem) ---------------------
__device__ float g_q [MROWS * AHS];
__device__ float g_k [MROWS * AHS];
__device__ float g_v [MROWS * AHS];
__device__ float g_co[MROWS * AHS];
__device__ float g_kc[MROWS * AHS];
__device__ float g_dw[MROWS * CIN];
__device__ float g_ck[MROWS * NHEAD * KTAPS];

// ------------------------- tf32 helpers ------------------------------------
__device__ __forceinline__ unsigned f2t(float x) {
    unsigned r;
    asm("cvt.rna.tf32.f32 %0, %1;" : "=r"(r) : "f"(x));
    return r;
}

__device__ __forceinline__ void mma_tf32(float* c, const unsigned* a, const unsigned* b) {
    asm volatile(
        "mma.sync.aligned.m16n8k8.row.col.f32.tf32.tf32.f32 "
        "{%0,%1,%2,%3}, {%4,%5,%6,%7}, {%8,%9}, {%0,%1,%2,%3};\n"
        : "+f"(c[0]), "+f"(c[1]), "+f"(c[2]), "+f"(c[3])
        : "r"(a[0]), "r"(a[1]), "r"(a[2]), "r"(a[3]), "r"(b[0]), "r"(b[1]));
}

// ------------------------- tf32 GEMM, grid.z selects weight set -------------
// C[z] = A[M x 768] @ W[z][768 x 384] + bias[z].  Tile 64x64, Kstep 32.
// 128 threads = 4 warps; warp w computes rows 16w..16w+15 x all 64 cols.
__global__ __launch_bounds__(128)
void gemm4_tf32(const float* __restrict__ A,
                const float* __restrict__ W0, const float* __restrict__ W1,
                const float* __restrict__ W2, const float* __restrict__ W3,
                const float* __restrict__ b0, const float* __restrict__ b1,
                const float* __restrict__ b2, const float* __restrict__ b3,
                float* __restrict__ O0, float* __restrict__ O1,
                float* __restrict__ O2, float* __restrict__ O3)
{
    const float* Ws[4] = {W0, W1, W2, W3};
    const float* bs[4] = {b0, b1, b2, b3};
    float*       Os[4] = {O0, O1, O2, O3};
    const int z = blockIdx.z;
    const float* B = Ws[z];
    const float* bias = bs[z];
    float* C = Os[z];

    __shared__ unsigned As[32][65];   // [k][m], transposed
    __shared__ unsigned Bs[32][68];   // [k][n]

    const int tid  = threadIdx.x;
    const int warp = tid >> 5;
    const int lane = tid & 31;
    const int g    = lane >> 2;
    const int tq   = lane & 3;
    const int m0 = blockIdx.y * 64;
    const int n0 = blockIdx.x * 64;

    float acc[8][4];
#pragma unroll
    for (int nc = 0; nc < 8; nc++)
#pragma unroll
        for (int i = 0; i < 4; i++) acc[nc][i] = 0.f;

    const int a_k4  = (tid & 7) * 4;     // 0..28
    const int a_rb  = tid >> 3;          // 0..15
    const int b_c4  = (tid & 15) * 4;    // 0..60
    const int b_rb  = tid >> 4;          // 0..7

    for (int k0 = 0; k0 < CIN; k0 += 32) {
        // load A tile 64x32 (transpose into As[k][m])
#pragma unroll
        for (int p = 0; p < 4; p++) {
            const int row = a_rb + 16 * p;
            float4 av = *(const float4*)(A + (size_t)(m0 + row) * CIN + k0 + a_k4);
            As[a_k4 + 0][row] = f2t(av.x);
            As[a_k4 + 1][row] = f2t(av.y);
            As[a_k4 + 2][row] = f2t(av.z);
            As[a_k4 + 3][row] = f2t(av.w);
        }
        // load B tile 32x64
#pragma unroll
        for (int p = 0; p < 4; p++) {
            const int row = b_rb + 8 * p;
            float4 bv = *(const float4*)(B + (size_t)(k0 + row) * AHS + n0 + b_c4);
            uint4 u;
            u.x = f2t(bv.x); u.y = f2t(bv.y); u.z = f2t(bv.z); u.w = f2t(bv.w);
            *(uint4*)&Bs[row][b_c4] = u;
        }
        __syncthreads();

#pragma unroll
        for (int kk = 0; kk < 4; kk++) {
            unsigned a[4];
            a[0] = As[kk * 8 + tq    ][warp * 16 + g    ];
            a[1] = As[kk * 8 + tq    ][warp * 16 + g + 8];
            a[2] = As[kk * 8 + tq + 4][warp * 16 + g    ];
            a[3] = As[kk * 8 + tq + 4][warp * 16 + g + 8];
#pragma unroll
            for (int nc = 0; nc < 8; nc++) {
                unsigned b[2];
                b[0] = Bs[kk * 8 + tq    ][nc * 8 + g];
                b[1] = Bs[kk * 8 + tq + 4][nc * 8 + g];
                mma_tf32(acc[nc], a, b);
            }
        }
        __syncthreads();
    }

    // epilogue
#pragma unroll
    for (int nc = 0; nc < 8; nc++) {
        const int col = n0 + nc * 8 + 2 * tq;
        const float bv0 = bias[col], bv1 = bias[col + 1];
        const int r0 = m0 + warp * 16 + g;
        float2 v0 = make_float2(acc[nc][0] + bv0, acc[nc][1] + bv1);
        float2 v1 = make_float2(acc[nc][2] + bv0, acc[nc][3] + bv1);
        *(float2*)(C + (size_t)r0 * AHS + col)       = v0;
        *(float2*)(C + (size_t)(r0 + 8) * AHS + col) = v1;
    }
}

// ------------------------- depthwise conv (K=9, SAME) ----------------------
__global__ void dwconv9(const float* __restrict__ hs, const float* __restrict__ w,
                        float* __restrict__ out)
{
    int idx = blockIdx.x * blockDim.x + threadIdx.x;
    if (idx >= MROWS * CIN) return;
    int c = idx % CIN;
    int s = (idx / CIN) & (SEQ - 1);
    int b = idx / (CIN * SEQ);
    float acc = 0.f;
#pragma unroll
    for (int t = 0; t < KTAPS; t++) {
        int ss = s + t - 4;
        if (ss >= 0 && ss < SEQ)
            acc += hs[((size_t)(b * SEQ + ss)) * CIN + c] * w[t * CIN + c];
    }
    out[idx] = acc;
}

// ---------------- span kernel: ck = softmax_K((kc*q) @ Wck + bck) ----------
__global__ __launch_bounds__(128)
void span_kernel(const float* __restrict__ kc, const float* __restrict__ q,
                 const float* __restrict__ Wck, const float* __restrict__ bck,
                 float* __restrict__ ck)
{
    const int row = blockIdx.x;
    __shared__ float a[AHS];
    __shared__ float sv[NHEAD * KTAPS];
    const int tid = threadIdx.x;

    for (int c = tid; c < AHS; c += 128)
        a[c] = kc[(size_t)row * AHS + c] * q[(size_t)row * AHS + c];
    __syncthreads();

    if (tid < NHEAD * KTAPS) {
        float acc = bck[tid];
#pragma unroll 4
        for (int c = 0; c < AHS; c++)
            acc += a[c] * Wck[c * (NHEAD * KTAPS) + tid];
        sv[tid] = acc;
    }
    __syncthreads();

    if (tid < NHEAD) {
        float m = -1e30f;
#pragma unroll
        for (int t = 0; t < KTAPS; t++) m = fmaxf(m, sv[tid * KTAPS + t]);
        float e[KTAPS]; float s = 0.f;
#pragma unroll
        for (int t = 0; t < KTAPS; t++) { e[t] = __expf(sv[tid * KTAPS + t] - m); s += e[t]; }
        const float inv = 1.f / s;
#pragma unroll
        for (int t = 0; t < KTAPS; t++)
            ck[(size_t)row * (NHEAD * KTAPS) + tid * KTAPS + t] = e[t] * inv;
    }
}

// ---------------- dynamic conv gather -> out[:, 384:768] -------------------
__global__ void dynconv(const float* __restrict__ ck, const float* __restrict__ co,
                        float* __restrict__ out)
{
    int idx = blockIdx.x * blockDim.x + threadIdx.x;
    if (idx >= MROWS * AHS) return;
    const int hd  = idx % AHS;
    const int row = idx / AHS;
    const int b = row >> 11;
    const int s = row & (SEQ - 1);
    const int h = hd >> 6;
    const float* ckr = ck + (size_t)row * (NHEAD * KTAPS) + h * KTAPS;
    float acc = 0.f;
#pragma unroll
    for (int t = 0; t < KTAPS; t++) {
        int ss = s + t - 4;
        float cv = (ss >= 0 && ss < SEQ) ? co[((size_t)(b * SEQ + ss)) * AHS + hd] : 0.f;
        acc = fmaf(ckr[t], cv, acc);
    }
    out[(size_t)row * (2 * AHS) + AHS + hd] = acc;
}

// ---------------- flash attention (tf32 mma) -> out[:, 0:384] --------------
// BQ=64 queries per block, BK=64 keys per iter, 128 threads = 4 warps.
// Warp w owns query rows q0+16w .. q0+16w+15.
struct AttnSmem {
    unsigned Ks[64][68];   // [key][dim], tf32
    unsigned Vs[64][68];   // [key][dim], tf32
    unsigned Ss[64][66];   // [q][key], P as tf32
    float    Ms[SEQ];      // attention mask row for this batch
};

__global__ __launch_bounds__(128)
void attn_tf32(const float* __restrict__ q, const float* __restrict__ k,
               const float* __restrict__ v, const float* __restrict__ mask,
               const float* __restrict__ headmask, float* __restrict__ out)
{
    extern __shared__ char smem_raw[];
    AttnSmem& sm = *reinterpret_cast<AttnSmem*>(smem_raw);

    const int tid  = threadIdx.x;
    const int warp = tid >> 5;
    const int lane = tid & 31;
    const int g    = lane >> 2;
    const int tq   = lane & 3;

    const int bh = blockIdx.y;
    const int b = bh / NHEAD, h = bh % NHEAD;
    const int q0 = blockIdx.x * 64;

    // mask row -> smem
    for (int i = tid; i < SEQ; i += 128)
        sm.Ms[i] = mask[(size_t)b * SEQ + i];

    // Q fragments (pre-scaled by 1/sqrt(D), converted to tf32)
    unsigned aq[8][4];
    {
        const float* qp = q + (size_t)(b * SEQ + q0 + warp * 16) * AHS + h * HDIM;
#pragma unroll
        for (int kc = 0; kc < 8; kc++) {
            aq[kc][0] = f2t(qp[(size_t)g       * AHS + kc * 8 + tq    ] * 0.125f);
            aq[kc][1] = f2t(qp[(size_t)(g + 8) * AHS + kc * 8 + tq    ] * 0.125f);
            aq[kc][2] = f2t(qp[(size_t)g       * AHS + kc * 8 + tq + 4] * 0.125f);
            aq[kc][3] = f2t(qp[(size_t)(g + 8) * AHS + kc * 8 + tq + 4] * 0.125f);
        }
    }

    float o[8][4];
#pragma unroll
    for (int nc = 0; nc < 8; nc++)
#pragma unroll
        for (int i = 0; i < 4; i++) o[nc][i] = 0.f;
    float mrun0 = -1e30f, mrun1 = -1e30f, l0 = 0.f, l1 = 0.f;

    const int kv_row  = tid >> 1;         // 0..63
    const int kv_half = (tid & 1) * 32;   // 0 or 32
    const float* kbase = k + (size_t)b * SEQ * AHS + h * HDIM;
    const float* vbase = v + (size_t)b * SEQ * AHS + h * HDIM;

    for (int kb = 0; kb < SEQ; kb += 64) {
        __syncthreads();   // previous iter's smem reads done
        // load K,V tiles (convert to tf32)
        {
            const float* kr = kbase + (size_t)(kb + kv_row) * AHS + kv_half;
            const float* vr = vbase + (size_t)(kb + kv_row) * AHS + kv_half;
#pragma unroll
            for (int f = 0; f < 8; f++) {
                float4 kv4 = *(const float4*)(kr + f * 4);
                uint4 u;
                u.x = f2t(kv4.x); u.y = f2t(kv4.y); u.z = f2t(kv4.z); u.w = f2t(kv4.w);
                *(uint4*)&sm.Ks[kv_row][kv_half + f * 4] = u;
                float4 vv4 = *(const float4*)(vr + f * 4);
                uint4 w;
                w.x = f2t(vv4.x); w.y = f2t(vv4.y); w.z = f2t(vv4.z); w.w = f2t(vv4.w);
                *(uint4*)&sm.Vs[kv_row][kv_half + f * 4] = w;
            }
        }
        __syncthreads();

        // ---- scores: S[16 x 64] = Q x K^T, plus mask ----
        float sfr[8][4];
#pragma unroll
        for (int nc = 0; nc < 8; nc++) {
            sfr[nc][0] = sfr[nc][1] = sfr[nc][2] = sfr[nc][3] = 0.f;
#pragma unroll
            for (int kc = 0; kc < 8; kc++) {
                unsigned bfr[2];
                bfr[0] = sm.Ks[nc * 8 + g][kc * 8 + tq    ];
                bfr[1] = sm.Ks[nc * 8 + g][kc * 8 + tq + 4];
                mma_tf32(sfr[nc], aq[kc], bfr);
            }
            const float m0v = sm.Ms[kb + nc * 8 + 2 * tq];
            const float m1v = sm.Ms[kb + nc * 8 + 2 * tq + 1];
            sfr[nc][0] += m0v; sfr[nc][1] += m1v;
            sfr[nc][2] += m0v; sfr[nc][3] += m1v;
        }

        // ---- online softmax (rows g and g+8) ----
        float rmax0 = -1e30f, rmax1 = -1e30f;
#pragma unroll
        for (int nc = 0; nc < 8; nc++) {
            rmax0 = fmaxf(rmax0, fmaxf(sfr[nc][0], sfr[nc][1]));
            rmax1 = fmaxf(rmax1, fmaxf(sfr[nc][2], sfr[nc][3]));
        }
        rmax0 = fmaxf(rmax0, __shfl_xor_sync(0xffffffffu, rmax0, 1));
        rmax0 = fmaxf(rmax0, __shfl_xor_sync(0xffffffffu, rmax0, 2));
        rmax1 = fmaxf(rmax1, __shfl_xor_sync(0xffffffffu, rmax1, 1));
        rmax1 = fmaxf(rmax1, __shfl_xor_sync(0xffffffffu, rmax1, 2));

        const float nm0 = fmaxf(mrun0, rmax0);
        const float nm1 = fmaxf(mrun1, rmax1);
        const float corr0 = __expf(mrun0 - nm0);
        const float corr1 = __expf(mrun1 - nm1);

        float rsum0 = 0.f, rsum1 = 0.f;
#pragma unroll
        for (int nc = 0; nc < 8; nc++) {
            float p0 = __expf(sfr[nc][0] - nm0);
            float p1 = __expf(sfr[nc][1] - nm0);
            float p2 = __expf(sfr[nc][2] - nm1);
            float p3 = __expf(sfr[nc][3] - nm1);
            rsum0 += p0 + p1;
            rsum1 += p2 + p3;
            uint2 u0 = make_uint2(f2t(p0), f2t(p1));
            uint2 u1 = make_uint2(f2t(p2), f2t(p3));
            *(uint2*)&sm.Ss[warp * 16 + g    ][nc * 8 + 2 * tq] = u0;
            *(uint2*)&sm.Ss[warp * 16 + g + 8][nc * 8 + 2 * tq] = u1;
        }
        rsum0 += __shfl_xor_sync(0xffffffffu, rsum0, 1);
        rsum0 += __shfl_xor_sync(0xffffffffu, rsum0, 2);
        rsum1 += __shfl_xor_sync(0xffffffffu, rsum1, 1);
        rsum1 += __shfl_xor_sync(0xffffffffu, rsum1, 2);

        l0 = l0 * corr0 + rsum0;
        l1 = l1 * corr1 + rsum1;
#pragma unroll
        for (int nc = 0; nc < 8; nc++) {
            o[nc][0] *= corr0; o[nc][1] *= corr0;
            o[nc][2] *= corr1; o[nc][3] *= corr1;
        }
        mrun0 = nm0; mrun1 = nm1;

        __syncwarp();   // Ss visible within warp

        // ---- PV: O[16 x 64] += P[16 x 64keys] x V[64keys x 64dim] ----
#pragma unroll
        for (int kc = 0; kc < 8; kc++) {
            unsigned ap[4];
            ap[0] = sm.Ss[warp * 16 + g    ][kc * 8 + tq    ];
            ap[1] = sm.Ss[warp * 16 + g + 8][kc * 8 + tq    ];
            ap[2] = sm.Ss[warp * 16 + g    ][kc * 8 + tq + 4];
            ap[3] = sm.Ss[warp * 16 + g + 8][kc * 8 + tq + 4];
#pragma unroll
            for (int nd = 0; nd < 8; nd++) {
                unsigned bfr[2];
                bfr[0] = sm.Vs[kc * 8 + tq    ][nd * 8 + g];
                bfr[1] = sm.Vs[kc * 8 + tq + 4][nd * 8 + g];
                mma_tf32(o[nd], ap, bfr);
            }
        }
    }

    // ---- epilogue: divide by l, apply head mask ----
    const float hm = headmask[h];
    const float inv0 = hm / l0;
    const float inv1 = hm / l1;
    const int r0 = b * SEQ + q0 + warp * 16 + g;
#pragma unroll
    for (int nd = 0; nd < 8; nd++) {
        const int col = h * HDIM + nd * 8 + 2 * tq;
        float2 v0 = make_float2(o[nd][0] * inv0, o[nd][1] * inv0);
        float2 v1 = make_float2(o[nd][2] * inv1, o[nd][3] * inv1);
        *(float2*)(out + (size_t)r0 * (2 * AHS) + col)       = v0;
        *(float2*)(out + (size_t)(r0 + 8) * (2 * AHS) + col) = v1;
    }
}

// ---------------------------------------------------------------------------
extern "C" void kernel_launch(void* const* d_in, const int* in_sizes, int n_in,
                              void* d_out, int out_size)
{
    const float* hs    = (const float*)d_in[0];
    const float* amask = (const float*)d_in[1];
    const float* hmask = (const float*)d_in[2];
    const float* Wq    = (const float*)d_in[3];
    const float* bq    = (const float*)d_in[4];
    const float* Wk    = (const float*)d_in[5];
    const float* bk    = (const float*)d_in[6];
    const float* Wv    = (const float*)d_in[7];
    const float* bv    = (const float*)d_in[8];
    const float* dwk   = (const float*)d_in[9];
    const float* pw    = (const float*)d_in[10];
    const float* cb    = (const float*)d_in[11];
    const float* Wck   = (const float*)d_in[12];
    const float* bck   = (const float*)d_in[13];
    const float* Wco   = (const float*)d_in[14];
    const float* bco   = (const float*)d_in[15];
    float* out = (float*)d_out;

    float *pq, *pk, *pv, *pco, *pkc, *pdw, *pck;
    cudaGetSymbolAddress((void**)&pq,  g_q);
    cudaGetSymbolAddress((void**)&pk,  g_k);
    cudaGetSymbolAddress((void**)&pv,  g_v);
    cudaGetSymbolAddress((void**)&pco, g_co);
    cudaGetSymbolAddress((void**)&pkc, g_kc);
    cudaGetSymbolAddress((void**)&pdw, g_dw);
    cudaGetSymbolAddress((void**)&pck, g_ck);

    cudaFuncSetAttribute(attn_tf32, cudaFuncAttributeMaxDynamicSharedMemorySize,
                         (int)sizeof(AttnSmem));

    // fused Q/K/V/CO projections (grid.z picks the weight set)
    gemm4_tf32<<<dim3(AHS / 64, MROWS / 64, 4), 128>>>(
        hs, Wq, Wk, Wv, Wco, bq, bk, bv, bco, pq, pk, pv, pco);

    {
        int n = MROWS * CIN;
        dwconv9<<<(n + 255) / 256, 256>>>(hs, dwk, pdw);
    }
    // pointwise projection after depthwise conv
    gemm4_tf32<<<dim3(AHS / 64, MROWS / 64, 1), 128>>>(
        pdw, pw, pw, pw, pw, cb, cb, cb, cb, pkc, pkc, pkc, pkc);

    span_kernel<<<MROWS, 128>>>(pkc, pq, Wck, bck, pck);

    {
        int n = MROWS * AHS;
        dynconv<<<(n + 255) / 256, 256>>>(pck, pco, out);
    }

    attn_tf32<<<dim3(SEQ / 64, BATCH * NHEAD), 128, sizeof(AttnSmem)>>>(
        pq, pk, pv, amask, hmask, out);
}

// round 3
// speedup vs baseline: 3.1779x; 1.3999x over previous
#include <cuda_runtime.h>
#include <cuda_bf16.h>

// ---------------------------------------------------------------------------
// TFConvBertSelfAttention  (B=4, S=2048, C=768, H=6, D=64, AHS=384, K=9)
// R3: pre-converted/permuted tf32 K,V; 8-warp flash attention; span as mma
//     GEMM; softmax fused into dynconv; float4 depthwise conv.
// ---------------------------------------------------------------------------

#define BATCH   4
#define SEQ     2048
#define CIN     768
#define NHEAD   6
#define HDIM    64
#define AHS     384
#define KTAPS   9
#define MROWS   (BATCH * SEQ)          // 8192

// ------------------------- scratch (static device mem) ---------------------
__device__ float    g_q [MROWS * AHS];
__device__ unsigned g_kt[MROWS * AHS];   // tf32, pair-permuted within 8-dim chunks
__device__ unsigned g_vt[MROWS * AHS];   // tf32, plain layout
__device__ float    g_co[MROWS * AHS];
__device__ float    g_kc[MROWS * AHS];
__device__ float    g_dw[MROWS * CIN];
__device__ float    g_ck[MROWS * 64];    // raw span logits (54 valid, stride 64)

// ------------------------- tf32 helpers ------------------------------------
__device__ __forceinline__ unsigned f2t(float x) {
    unsigned r;
    asm("cvt.rna.tf32.f32 %0, %1;" : "=r"(r) : "f"(x));
    return r;
}

__device__ __forceinline__ void mma_tf32(float* c, const unsigned* a, const unsigned* b) {
    asm volatile(
        "mma.sync.aligned.m16n8k8.row.col.f32.tf32.tf32.f32 "
        "{%0,%1,%2,%3}, {%4,%5,%6,%7}, {%8,%9}, {%0,%1,%2,%3};\n"
        : "+f"(c[0]), "+f"(c[1]), "+f"(c[2]), "+f"(c[3])
        : "r"(a[0]), "r"(a[1]), "r"(a[2]), "r"(a[3]), "r"(b[0]), "r"(b[1]));
}

// ------------------------- tf32 GEMM, grid.z selects weight set -------------
// z=0: q (float+bias)   z=1: k -> g_kt (tf32, permuted)
// z=2: v -> g_vt (tf32) z=3: co (float+bias)
__global__ __launch_bounds__(128)
void gemm4_tf32(const float* __restrict__ A,
                const float* __restrict__ W0, const float* __restrict__ W1,
                const float* __restrict__ W2, const float* __restrict__ W3,
                const float* __restrict__ b0, const float* __restrict__ b1,
                const float* __restrict__ b2, const float* __restrict__ b3,
                float* __restrict__ Oq, unsigned* __restrict__ Okt,
                unsigned* __restrict__ Ovt, float* __restrict__ Oco)
{
    const float* Ws[4] = {W0, W1, W2, W3};
    const float* bs[4] = {b0, b1, b2, b3};
    const int z = blockIdx.z;
    const float* B = Ws[z];
    const float* bias = bs[z];

    __shared__ unsigned As[32][65];   // [k][m], transposed
    __shared__ unsigned Bs[32][68];   // [k][n]

    const int tid  = threadIdx.x;
    const int warp = tid >> 5;
    const int lane = tid & 31;
    const int g    = lane >> 2;
    const int tq   = lane & 3;
    const int m0 = blockIdx.y * 64;
    const int n0 = blockIdx.x * 64;

    float acc[8][4];
#pragma unroll
    for (int nc = 0; nc < 8; nc++)
#pragma unroll
        for (int i = 0; i < 4; i++) acc[nc][i] = 0.f;

    const int a_k4  = (tid & 7) * 4;
    const int a_rb  = tid >> 3;
    const int b_c4  = (tid & 15) * 4;
    const int b_rb  = tid >> 4;

    for (int k0 = 0; k0 < CIN; k0 += 32) {
#pragma unroll
        for (int p = 0; p < 4; p++) {
            const int row = a_rb + 16 * p;
            float4 av = *(const float4*)(A + (size_t)(m0 + row) * CIN + k0 + a_k4);
            As[a_k4 + 0][row] = f2t(av.x);
            As[a_k4 + 1][row] = f2t(av.y);
            As[a_k4 + 2][row] = f2t(av.z);
            As[a_k4 + 3][row] = f2t(av.w);
        }
#pragma unroll
        for (int p = 0; p < 4; p++) {
            const int row = b_rb + 8 * p;
            float4 bv = *(const float4*)(B + (size_t)(k0 + row) * AHS + n0 + b_c4);
            uint4 u;
            u.x = f2t(bv.x); u.y = f2t(bv.y); u.z = f2t(bv.z); u.w = f2t(bv.w);
            *(uint4*)&Bs[row][b_c4] = u;
        }
        __syncthreads();

#pragma unroll
        for (int kk = 0; kk < 4; kk++) {
            unsigned a[4];
            a[0] = As[kk * 8 + tq    ][warp * 16 + g    ];
            a[1] = As[kk * 8 + tq    ][warp * 16 + g + 8];
            a[2] = As[kk * 8 + tq + 4][warp * 16 + g    ];
            a[3] = As[kk * 8 + tq + 4][warp * 16 + g + 8];
#pragma unroll
            for (int nc = 0; nc < 8; nc++) {
                unsigned b[2];
                b[0] = Bs[kk * 8 + tq    ][nc * 8 + g];
                b[1] = Bs[kk * 8 + tq + 4][nc * 8 + g];
                mma_tf32(acc[nc], a, b);
            }
        }
        __syncthreads();
    }

    const int r0 = m0 + warp * 16 + g;
    if (z == 0 || z == 3) {
        float* C = (z == 0) ? Oq : Oco;
#pragma unroll
        for (int nc = 0; nc < 8; nc++) {
            const int col = n0 + nc * 8 + 2 * tq;
            const float bv0 = bias[col], bv1 = bias[col + 1];
            *(float2*)(C + (size_t)r0 * AHS + col) =
                make_float2(acc[nc][0] + bv0, acc[nc][1] + bv1);
            *(float2*)(C + (size_t)(r0 + 8) * AHS + col) =
                make_float2(acc[nc][2] + bv0, acc[nc][3] + bv1);
        }
    } else if (z == 1) {
        // permuted tf32: within each 8-col chunk, value at t' goes to
        // 2*(t'&3) + (t'>>2).  Thread cols 2tq, 2tq+1 -> base, base+2.
        const int base_off = (tq < 2) ? 4 * tq : 4 * tq - 7;
#pragma unroll
        for (int nc = 0; nc < 8; nc++) {
            const int col = n0 + nc * 8 + 2 * tq;
            const float bv0 = bias[col], bv1 = bias[col + 1];
            const int pos = n0 + nc * 8 + base_off;
            Okt[(size_t)r0 * AHS + pos]           = f2t(acc[nc][0] + bv0);
            Okt[(size_t)r0 * AHS + pos + 2]       = f2t(acc[nc][1] + bv1);
            Okt[(size_t)(r0 + 8) * AHS + pos]     = f2t(acc[nc][2] + bv0);
            Okt[(size_t)(r0 + 8) * AHS + pos + 2] = f2t(acc[nc][3] + bv1);
        }
    } else {
#pragma unroll
        for (int nc = 0; nc < 8; nc++) {
            const int col = n0 + nc * 8 + 2 * tq;
            const float bv0 = bias[col], bv1 = bias[col + 1];
            *(uint2*)(Ovt + (size_t)r0 * AHS + col) =
                make_uint2(f2t(acc[nc][0] + bv0), f2t(acc[nc][1] + bv1));
            *(uint2*)(Ovt + (size_t)(r0 + 8) * AHS + col) =
                make_uint2(f2t(acc[nc][2] + bv0), f2t(acc[nc][3] + bv1));
        }
    }
}

// ------------------------- depthwise conv (K=9, SAME), float4 --------------
__global__ void dwconv9v4(const float* __restrict__ hs, const float* __restrict__ w,
                          float* __restrict__ out)
{
    int idx = blockIdx.x * blockDim.x + threadIdx.x;
    if (idx >= MROWS * CIN / 4) return;
    const int c4  = idx % (CIN / 4);
    const int row = idx / (CIN / 4);
    const int s = row & (SEQ - 1);
    const int b = row >> 11;
    float4 acc = make_float4(0.f, 0.f, 0.f, 0.f);
#pragma unroll
    for (int t = 0; t < KTAPS; t++) {
        int ss = s + t - 4;
        if (ss >= 0 && ss < SEQ) {
            float4 x  = *(const float4*)(hs + ((size_t)(b * SEQ + ss)) * CIN + c4 * 4);
            float4 wv = *(const float4*)(w + t * CIN + c4 * 4);
            acc.x = fmaf(x.x, wv.x, acc.x);
            acc.y = fmaf(x.y, wv.y, acc.y);
            acc.z = fmaf(x.z, wv.z, acc.z);
            acc.w = fmaf(x.w, wv.w, acc.w);
        }
    }
    *(float4*)(out + (size_t)idx * 4) = acc;
}

// ---------------- span GEMM: logits = (kc*q) @ Wck + bck -------------------
// M=8192, N=54 (padded 64), K=384.  Raw float logits -> g_ck (stride 64).
__global__ __launch_bounds__(128)
void span_gemm(const float* __restrict__ kc, const float* __restrict__ q,
               const float* __restrict__ Wck, const float* __restrict__ bck,
               float* __restrict__ ck)
{
    __shared__ unsigned As[32][65];
    __shared__ unsigned Bs[32][68];

    const int tid  = threadIdx.x;
    const int warp = tid >> 5;
    const int lane = tid & 31;
    const int g    = lane >> 2;
    const int tq   = lane & 3;
    const int m0 = blockIdx.x * 64;

    // zero pad cols 54..63 once
    for (int i = tid; i < 32 * 10; i += 128)
        Bs[i / 10][54 + i % 10] = 0u;

    float acc[8][4];
#pragma unroll
    for (int nc = 0; nc < 8; nc++)
#pragma unroll
        for (int i = 0; i < 4; i++) acc[nc][i] = 0.f;

    const int a_k4 = (tid & 7) * 4;
    const int a_rb = tid >> 3;
    const int NCK = NHEAD * KTAPS;   // 54

    for (int k0 = 0; k0 < AHS; k0 += 32) {
#pragma unroll
        for (int p = 0; p < 4; p++) {
            const int row = a_rb + 16 * p;
            float4 xv = *(const float4*)(kc + (size_t)(m0 + row) * AHS + k0 + a_k4);
            float4 qv = *(const float4*)(q  + (size_t)(m0 + row) * AHS + k0 + a_k4);
            As[a_k4 + 0][row] = f2t(xv.x * qv.x);
            As[a_k4 + 1][row] = f2t(xv.y * qv.y);
            As[a_k4 + 2][row] = f2t(xv.z * qv.z);
            As[a_k4 + 3][row] = f2t(xv.w * qv.w);
        }
        for (int i = tid; i < 32 * NCK; i += 128) {
            const int r = i / NCK, c = i % NCK;
            Bs[r][c] = f2t(Wck[(size_t)(k0 + r) * NCK + c]);
        }
        __syncthreads();

#pragma unroll
        for (int kk = 0; kk < 4; kk++) {
            unsigned a[4];
            a[0] = As[kk * 8 + tq    ][warp * 16 + g    ];
            a[1] = As[kk * 8 + tq    ][warp * 16 + g + 8];
            a[2] = As[kk * 8 + tq + 4][warp * 16 + g    ];
            a[3] = As[kk * 8 + tq + 4][warp * 16 + g + 8];
#pragma unroll
            for (int nc = 0; nc < 8; nc++) {
                unsigned b[2];
                b[0] = Bs[kk * 8 + tq    ][nc * 8 + g];
                b[1] = Bs[kk * 8 + tq + 4][nc * 8 + g];
                mma_tf32(acc[nc], a, b);
            }
        }
        __syncthreads();
    }

    const int r0 = m0 + warp * 16 + g;
#pragma unroll
    for (int nc = 0; nc < 8; nc++) {
        const int col = nc * 8 + 2 * tq;
        if (col < NCK) {
            const float bv0 = bck[col], bv1 = bck[col + 1];
            ck[(size_t)r0 * 64 + col]           = acc[nc][0] + bv0;
            ck[(size_t)r0 * 64 + col + 1]       = acc[nc][1] + bv1;
            ck[(size_t)(r0 + 8) * 64 + col]     = acc[nc][2] + bv0;
            ck[(size_t)(r0 + 8) * 64 + col + 1] = acc[nc][3] + bv1;
        }
    }
}

// ---------------- softmax + dynamic conv -> out[:, 384:768] ----------------
__global__ __launch_bounds__(384)
void dynsoft(const float* __restrict__ ckraw, const float* __restrict__ co,
             float* __restrict__ out)
{
    const int row = blockIdx.x;
    const int tid = threadIdx.x;
    __shared__ float p[NHEAD * KTAPS];

    if (tid < NHEAD) {
        const float* lr = ckraw + (size_t)row * 64 + tid * KTAPS;
        float m = -1e30f;
#pragma unroll
        for (int t = 0; t < KTAPS; t++) m = fmaxf(m, lr[t]);
        float e[KTAPS], s = 0.f;
#pragma unroll
        for (int t = 0; t < KTAPS; t++) { e[t] = __expf(lr[t] - m); s += e[t]; }
        const float inv = 1.f / s;
#pragma unroll
        for (int t = 0; t < KTAPS; t++) p[tid * KTAPS + t] = e[t] * inv;
    }
    __syncthreads();

    const int hd = tid;
    const int h = hd >> 6;
    const int b = row >> 11;
    const int s = row & (SEQ - 1);
    float acc = 0.f;
#pragma unroll
    for (int t = 0; t < KTAPS; t++) {
        int ss = s + t - 4;
        float cv = (ss >= 0 && ss < SEQ) ? co[((size_t)(b * SEQ + ss)) * AHS + hd] : 0.f;
        acc = fmaf(p[h * KTAPS + t], cv, acc);
    }
    out[(size_t)row * (2 * AHS) + AHS + hd] = acc;
}

// ---------------- flash attention (tf32 mma) -> out[:, 0:384] --------------
// BQ=128 (8 warps x 16 rows), BK=64.  K pre-permuted tf32, V tf32.
struct AttnSmem {
    unsigned Ks[64][72];   // permuted: uint2 at [key][kc*8+2tq] = (b0,b1)
    unsigned Vs[64][72];
    unsigned Ss[128][68];
    float    Ms[SEQ];
};

__global__ __launch_bounds__(256)
void attn_tf32(const float* __restrict__ q, const unsigned* __restrict__ kt,
               const unsigned* __restrict__ vt, const float* __restrict__ mask,
               const float* __restrict__ headmask, float* __restrict__ out)
{
    extern __shared__ char smem_raw[];
    AttnSmem& sm = *reinterpret_cast<AttnSmem*>(smem_raw);

    const int tid  = threadIdx.x;
    const int warp = tid >> 5;
    const int lane = tid & 31;
    const int g    = lane >> 2;
    const int tq   = lane & 3;

    const int bh = blockIdx.y;
    const int b = bh / NHEAD, h = bh % NHEAD;
    const int q0 = blockIdx.x * 128;

    for (int i = tid; i < SEQ; i += 256)
        sm.Ms[i] = mask[(size_t)b * SEQ + i];

    // Q fragments (pre-scaled, tf32)
    unsigned aq[8][4];
    {
        const float* qp = q + (size_t)(b * SEQ + q0 + warp * 16) * AHS + h * HDIM;
#pragma unroll
        for (int kc = 0; kc < 8; kc++) {
            aq[kc][0] = f2t(qp[(size_t)g       * AHS + kc * 8 + tq    ] * 0.125f);
            aq[kc][1] = f2t(qp[(size_t)(g + 8) * AHS + kc * 8 + tq    ] * 0.125f);
            aq[kc][2] = f2t(qp[(size_t)g       * AHS + kc * 8 + tq + 4] * 0.125f);
            aq[kc][3] = f2t(qp[(size_t)(g + 8) * AHS + kc * 8 + tq + 4] * 0.125f);
        }
    }

    float o[8][4];
#pragma unroll
    for (int nc = 0; nc < 8; nc++)
#pragma unroll
        for (int i = 0; i < 4; i++) o[nc][i] = 0.f;
    float mrun0 = -1e30f, mrun1 = -1e30f, l0 = 0.f, l1 = 0.f;

    const int lrow = tid >> 2;            // 0..63
    const int lseg = (tid & 3) * 16;      // 0,16,32,48
    const unsigned* kbase = kt + (size_t)b * SEQ * AHS + h * HDIM;
    const unsigned* vbase = vt + (size_t)b * SEQ * AHS + h * HDIM;

    for (int kb = 0; kb < SEQ; kb += 64) {
        __syncthreads();
        {
            const unsigned* kr = kbase + (size_t)(kb + lrow) * AHS + lseg;
            const unsigned* vr = vbase + (size_t)(kb + lrow) * AHS + lseg;
#pragma unroll
            for (int f = 0; f < 4; f++) {
                *(uint4*)&sm.Ks[lrow][lseg + f * 4] = *(const uint4*)(kr + f * 4);
                *(uint4*)&sm.Vs[lrow][lseg + f * 4] = *(const uint4*)(vr + f * 4);
            }
        }
        __syncthreads();

        // ---- scores ----
        float sfr[8][4];
#pragma unroll
        for (int nc = 0; nc < 8; nc++) {
            sfr[nc][0] = sfr[nc][1] = sfr[nc][2] = sfr[nc][3] = 0.f;
#pragma unroll
            for (int kc = 0; kc < 8; kc++) {
                uint2 bb = *(const uint2*)&sm.Ks[nc * 8 + g][kc * 8 + 2 * tq];
                mma_tf32(sfr[nc], aq[kc], (const unsigned*)&bb);
            }
            const float m0v = sm.Ms[kb + nc * 8 + 2 * tq];
            const float m1v = sm.Ms[kb + nc * 8 + 2 * tq + 1];
            sfr[nc][0] += m0v; sfr[nc][1] += m1v;
            sfr[nc][2] += m0v; sfr[nc][3] += m1v;
        }

        // ---- online softmax ----
        float rmax0 = -1e30f, rmax1 = -1e30f;
#pragma unroll
        for (int nc = 0; nc < 8; nc++) {
            rmax0 = fmaxf(rmax0, fmaxf(sfr[nc][0], sfr[nc][1]));
            rmax1 = fmaxf(rmax1, fmaxf(sfr[nc][2], sfr[nc][3]));
        }
        rmax0 = fmaxf(rmax0, __shfl_xor_sync(0xffffffffu, rmax0, 1));
        rmax0 = fmaxf(rmax0, __shfl_xor_sync(0xffffffffu, rmax0, 2));
        rmax1 = fmaxf(rmax1, __shfl_xor_sync(0xffffffffu, rmax1, 1));
        rmax1 = fmaxf(rmax1, __shfl_xor_sync(0xffffffffu, rmax1, 2));

        const float nm0 = fmaxf(mrun0, rmax0);
        const float nm1 = fmaxf(mrun1, rmax1);
        const float corr0 = __expf(mrun0 - nm0);
        const float corr1 = __expf(mrun1 - nm1);

        float rsum0 = 0.f, rsum1 = 0.f;
#pragma unroll
        for (int nc = 0; nc < 8; nc++) {
            float p0 = __expf(sfr[nc][0] - nm0);
            float p1 = __expf(sfr[nc][1] - nm0);
            float p2 = __expf(sfr[nc][2] - nm1);
            float p3 = __expf(sfr[nc][3] - nm1);
            rsum0 += p0 + p1;
            rsum1 += p2 + p3;
            *(uint2*)&sm.Ss[warp * 16 + g    ][nc * 8 + 2 * tq] = make_uint2(f2t(p0), f2t(p1));
            *(uint2*)&sm.Ss[warp * 16 + g + 8][nc * 8 + 2 * tq] = make_uint2(f2t(p2), f2t(p3));
        }
        rsum0 += __shfl_xor_sync(0xffffffffu, rsum0, 1);
        rsum0 += __shfl_xor_sync(0xffffffffu, rsum0, 2);
        rsum1 += __shfl_xor_sync(0xffffffffu, rsum1, 1);
        rsum1 += __shfl_xor_sync(0xffffffffu, rsum1, 2);

        l0 = l0 * corr0 + rsum0;
        l1 = l1 * corr1 + rsum1;
#pragma unroll
        for (int nc = 0; nc < 8; nc++) {
            o[nc][0] *= corr0; o[nc][1] *= corr0;
            o[nc][2] *= corr1; o[nc][3] *= corr1;
        }
        mrun0 = nm0; mrun1 = nm1;

        __syncwarp();

        // ---- PV ----
#pragma unroll
        for (int kc = 0; kc < 8; kc++) {
            unsigned ap[4];
            ap[0] = sm.Ss[warp * 16 + g    ][kc * 8 + tq    ];
            ap[1] = sm.Ss[warp * 16 + g + 8][kc * 8 + tq    ];
            ap[2] = sm.Ss[warp * 16 + g    ][kc * 8 + tq + 4];
            ap[3] = sm.Ss[warp * 16 + g + 8][kc * 8 + tq + 4];
#pragma unroll
            for (int nd = 0; nd < 8; nd++) {
                unsigned bfr[2];
                bfr[0] = sm.Vs[kc * 8 + tq    ][nd * 8 + g];
                bfr[1] = sm.Vs[kc * 8 + tq + 4][nd * 8 + g];
                mma_tf32(o[nd], ap, bfr);
            }
        }
    }

    const float hm = headmask[h];
    const float inv0 = hm / l0;
    const float inv1 = hm / l1;
    const int r0 = b * SEQ + q0 + warp * 16 + g;
#pragma unroll
    for (int nd = 0; nd < 8; nd++) {
        const int col = h * HDIM + nd * 8 + 2 * tq;
        *(float2*)(out + (size_t)r0 * (2 * AHS) + col) =
            make_float2(o[nd][0] * inv0, o[nd][1] * inv0);
        *(float2*)(out + (size_t)(r0 + 8) * (2 * AHS) + col) =
            make_float2(o[nd][2] * inv1, o[nd][3] * inv1);
    }
}

// ---------------------------------------------------------------------------
extern "C" void kernel_launch(void* const* d_in, const int* in_sizes, int n_in,
                              void* d_out, int out_size)
{
    const float* hs    = (const float*)d_in[0];
    const float* amask = (const float*)d_in[1];
    const float* hmask = (const float*)d_in[2];
    const float* Wq    = (const float*)d_in[3];
    const float* bq    = (const float*)d_in[4];
    const float* Wk    = (const float*)d_in[5];
    const float* bk    = (const float*)d_in[6];
    const float* Wv    = (const float*)d_in[7];
    const float* bv    = (const float*)d_in[8];
    const float* dwk   = (const float*)d_in[9];
    const float* pw    = (const float*)d_in[10];
    const float* cb    = (const float*)d_in[11];
    const float* Wck   = (const float*)d_in[12];
    const float* bck   = (const float*)d_in[13];
    const float* Wco   = (const float*)d_in[14];
    const float* bco   = (const float*)d_in[15];
    float* out = (float*)d_out;

    float *pq, *pco, *pkc, *pdw, *pck;
    unsigned *pkt, *pvt;
    cudaGetSymbolAddress((void**)&pq,  g_q);
    cudaGetSymbolAddress((void**)&pkt, g_kt);
    cudaGetSymbolAddress((void**)&pvt, g_vt);
    cudaGetSymbolAddress((void**)&pco, g_co);
    cudaGetSymbolAddress((void**)&pkc, g_kc);
    cudaGetSymbolAddress((void**)&pdw, g_dw);
    cudaGetSymbolAddress((void**)&pck, g_ck);

    cudaFuncSetAttribute(attn_tf32, cudaFuncAttributeMaxDynamicSharedMemorySize,
                         (int)sizeof(AttnSmem));

    // 1: fused Q/K/V/CO projections
    gemm4_tf32<<<dim3(AHS / 64, MROWS / 64, 4), 128>>>(
        hs, Wq, Wk, Wv, Wco, bq, bk, bv, bco, pq, pkt, pvt, pco);

    // 2: depthwise conv
    {
        int n = MROWS * CIN / 4;
        dwconv9v4<<<(n + 255) / 256, 256>>>(hs, dwk, pdw);
    }

    // 3: pointwise projection (z=0 -> float path into pkc)
    gemm4_tf32<<<dim3(AHS / 64, MROWS / 64, 1), 128>>>(
        pdw, pw, pw, pw, pw, cb, cb, cb, cb, pkc, pkt, pvt, pco);

    // 4: span logits GEMM
    span_gemm<<<MROWS / 64, 128>>>(pkc, pq, Wck, bck, pck);

    // 5: softmax + dynamic conv
    dynsoft<<<MROWS, 384>>>(pck, pco, out);

    // 6: flash attention (profiled slot)
    attn_tf32<<<dim3(SEQ / 128, BATCH * NHEAD), 256, sizeof(AttnSmem)>>>(
        pq, pkt, pvt, amask, hmask, out);
}

// round 4
// speedup vs baseline: 3.3958x; 1.0686x over previous
#include <cuda_runtime.h>
#include <cuda_bf16.h>

// ---------------------------------------------------------------------------
// TFConvBertSelfAttention  (B=4, S=2048, C=768, H=6, D=64, AHS=384, K=9)
// R4: register-prefetch pipelined GEMMs, persistent-Wck span GEMM,
//     cp.async double-buffered attention (2 blocks/SM), smem-tiled convs.
// ---------------------------------------------------------------------------

#define BATCH   4
#define SEQ     2048
#define CIN     768
#define NHEAD   6
#define HDIM    64
#define AHS     384
#define KTAPS   9
#define MROWS   (BATCH * SEQ)          // 8192

// ------------------------- scratch (static device mem) ---------------------
__device__ float    g_q [MROWS * AHS];
__device__ unsigned g_kt[MROWS * AHS];   // tf32, pair-permuted within 8-dim chunks
__device__ unsigned g_vt[MROWS * AHS];   // tf32, plain layout
__device__ float    g_co[MROWS * AHS];
__device__ float    g_kc[MROWS * AHS];
__device__ float    g_dw[MROWS * CIN];
__device__ float    g_ck[MROWS * 64];    // raw span logits (54 valid, stride 64)

// ------------------------- helpers -----------------------------------------
__device__ __forceinline__ unsigned f2t(float x) {
    unsigned r;
    asm("cvt.rna.tf32.f32 %0, %1;" : "=r"(r) : "f"(x));
    return r;
}

__device__ __forceinline__ void mma_tf32(float* c, const unsigned* a, const unsigned* b) {
    asm volatile(
        "mma.sync.aligned.m16n8k8.row.col.f32.tf32.tf32.f32 "
        "{%0,%1,%2,%3}, {%4,%5,%6,%7}, {%8,%9}, {%0,%1,%2,%3};\n"
        : "+f"(c[0]), "+f"(c[1]), "+f"(c[2]), "+f"(c[3])
        : "r"(a[0]), "r"(a[1]), "r"(a[2]), "r"(a[3]), "r"(b[0]), "r"(b[1]));
}

__device__ __forceinline__ void cpa16(void* sm, const void* g) {
    unsigned sa = (unsigned)__cvta_generic_to_shared(sm);
    asm volatile("cp.async.cg.shared.global [%0], [%1], 16;" :: "r"(sa), "l"(g));
}

// ------------------------- tf32 GEMM, grid.z selects weight set -------------
// z=0: q/pkc (float+bias)  z=1: k -> g_kt (tf32, permuted)
// z=2: v -> g_vt (tf32)    z=3: co (float+bias)
__global__ __launch_bounds__(128)
void gemm4_tf32(const float* __restrict__ A,
                const float* __restrict__ W0, const float* __restrict__ W1,
                const float* __restrict__ W2, const float* __restrict__ W3,
                const float* __restrict__ b0, const float* __restrict__ b1,
                const float* __restrict__ b2, const float* __restrict__ b3,
                float* __restrict__ Oq, unsigned* __restrict__ Okt,
                unsigned* __restrict__ Ovt, float* __restrict__ Oco)
{
    const float* Ws[4] = {W0, W1, W2, W3};
    const float* bs[4] = {b0, b1, b2, b3};
    const int z = blockIdx.z;
    const float* B = Ws[z];
    const float* bias = bs[z];

    __shared__ unsigned As[32][65];   // [k][m], transposed
    __shared__ unsigned Bs[32][68];   // [k][n]

    const int tid  = threadIdx.x;
    const int warp = tid >> 5;
    const int lane = tid & 31;
    const int g    = lane >> 2;
    const int tq   = lane & 3;
    const int m0 = blockIdx.y * 64;
    const int n0 = blockIdx.x * 64;

    float acc[8][4];
#pragma unroll
    for (int nc = 0; nc < 8; nc++)
#pragma unroll
        for (int i = 0; i < 4; i++) acc[nc][i] = 0.f;

    const int a_k4  = (tid & 7) * 4;
    const int a_rb  = tid >> 3;
    const int b_c4  = (tid & 15) * 4;
    const int b_rb  = tid >> 4;

    float4 ar[4], br[4];
    // prologue prefetch k0 = 0
#pragma unroll
    for (int p = 0; p < 4; p++)
        ar[p] = *(const float4*)(A + (size_t)(m0 + a_rb + 16 * p) * CIN + a_k4);
#pragma unroll
    for (int p = 0; p < 4; p++)
        br[p] = *(const float4*)(B + (size_t)(b_rb + 8 * p) * AHS + n0 + b_c4);

    for (int k0 = 0; k0 < CIN; k0 += 32) {
        // store prefetched regs to smem (with tf32 cvt)
#pragma unroll
        for (int p = 0; p < 4; p++) {
            const int row = a_rb + 16 * p;
            As[a_k4 + 0][row] = f2t(ar[p].x);
            As[a_k4 + 1][row] = f2t(ar[p].y);
            As[a_k4 + 2][row] = f2t(ar[p].z);
            As[a_k4 + 3][row] = f2t(ar[p].w);
        }
#pragma unroll
        for (int p = 0; p < 4; p++) {
            uint4 u;
            u.x = f2t(br[p].x); u.y = f2t(br[p].y);
            u.z = f2t(br[p].z); u.w = f2t(br[p].w);
            *(uint4*)&Bs[b_rb + 8 * p][b_c4] = u;
        }
        __syncthreads();

        // prefetch next tile into regs (overlaps with mma below)
        if (k0 + 32 < CIN) {
#pragma unroll
            for (int p = 0; p < 4; p++)
                ar[p] = *(const float4*)(A + (size_t)(m0 + a_rb + 16 * p) * CIN + k0 + 32 + a_k4);
#pragma unroll
            for (int p = 0; p < 4; p++)
                br[p] = *(const float4*)(B + (size_t)(k0 + 32 + b_rb + 8 * p) * AHS + n0 + b_c4);
        }

#pragma unroll
        for (int kk = 0; kk < 4; kk++) {
            unsigned a[4];
            a[0] = As[kk * 8 + tq    ][warp * 16 + g    ];
            a[1] = As[kk * 8 + tq    ][warp * 16 + g + 8];
            a[2] = As[kk * 8 + tq + 4][warp * 16 + g    ];
            a[3] = As[kk * 8 + tq + 4][warp * 16 + g + 8];
#pragma unroll
            for (int nc = 0; nc < 8; nc++) {
                unsigned b[2];
                b[0] = Bs[kk * 8 + tq    ][nc * 8 + g];
                b[1] = Bs[kk * 8 + tq + 4][nc * 8 + g];
                mma_tf32(acc[nc], a, b);
            }
        }
        __syncthreads();
    }

    const int r0 = m0 + warp * 16 + g;
    if (z == 0 || z == 3) {
        float* C = (z == 0) ? Oq : Oco;
#pragma unroll
        for (int nc = 0; nc < 8; nc++) {
            const int col = n0 + nc * 8 + 2 * tq;
            const float bv0 = bias[col], bv1 = bias[col + 1];
            *(float2*)(C + (size_t)r0 * AHS + col) =
                make_float2(acc[nc][0] + bv0, acc[nc][1] + bv1);
            *(float2*)(C + (size_t)(r0 + 8) * AHS + col) =
                make_float2(acc[nc][2] + bv0, acc[nc][3] + bv1);
        }
    } else if (z == 1) {
        const int base_off = (tq < 2) ? 4 * tq : 4 * tq - 7;
#pragma unroll
        for (int nc = 0; nc < 8; nc++) {
            const int col = n0 + nc * 8 + 2 * tq;
            const float bv0 = bias[col], bv1 = bias[col + 1];
            const int pos = n0 + nc * 8 + base_off;
            Okt[(size_t)r0 * AHS + pos]           = f2t(acc[nc][0] + bv0);
            Okt[(size_t)r0 * AHS + pos + 2]       = f2t(acc[nc][1] + bv1);
            Okt[(size_t)(r0 + 8) * AHS + pos]     = f2t(acc[nc][2] + bv0);
            Okt[(size_t)(r0 + 8) * AHS + pos + 2] = f2t(acc[nc][3] + bv1);
        }
    } else {
#pragma unroll
        for (int nc = 0; nc < 8; nc++) {
            const int col = n0 + nc * 8 + 2 * tq;
            const float bv0 = bias[col], bv1 = bias[col + 1];
            *(uint2*)(Ovt + (size_t)r0 * AHS + col) =
                make_uint2(f2t(acc[nc][0] + bv0), f2t(acc[nc][1] + bv1));
            *(uint2*)(Ovt + (size_t)(r0 + 8) * AHS + col) =
                make_uint2(f2t(acc[nc][2] + bv0), f2t(acc[nc][3] + bv1));
        }
    }
}

// ------------------------- depthwise conv, smem tiled ----------------------
// grid (CIN/256, MROWS/32), 256 threads: thread = one channel, 32 s-rows.
__global__ __launch_bounds__(256)
void dwconv9s(const float* __restrict__ hs, const float* __restrict__ w,
              float* __restrict__ out)
{
    __shared__ float tile[40][256];
    const int tid = threadIdx.x;
    const int c0  = blockIdx.x * 256;
    const int row0 = blockIdx.y * 32;
    const int b = row0 >> 11;
    const int s0 = row0 & (SEQ - 1);

    for (int i = tid; i < 40 * 256; i += 256) {
        const int r = i >> 8, c = i & 255;
        const int ss = s0 + r - 4;
        tile[r][c] = (ss >= 0 && ss < SEQ)
            ? hs[(size_t)(b * SEQ + ss) * CIN + c0 + c] : 0.f;
    }
    float wr[KTAPS];
#pragma unroll
    for (int t = 0; t < KTAPS; t++) wr[t] = w[t * CIN + c0 + tid];
    __syncthreads();

#pragma unroll 4
    for (int si = 0; si < 32; si++) {
        float acc = 0.f;
#pragma unroll
        for (int t = 0; t < KTAPS; t++)
            acc = fmaf(tile[si + t][tid], wr[t], acc);
        out[(size_t)(row0 + si) * CIN + c0 + tid] = acc;
    }
}

// ---------------- span GEMM: logits = (kc*q) @ Wck + bck -------------------
// Wck held resident in smem (loaded once); A-tiles register-prefetched.
struct SpanSmem {
    unsigned As[32][65];
    unsigned Bw[384][72];
};

__global__ __launch_bounds__(128)
void span_gemm(const float* __restrict__ kc, const float* __restrict__ q,
               const float* __restrict__ Wck, const float* __restrict__ bck,
               float* __restrict__ ck)
{
    extern __shared__ char smem_raw[];
    SpanSmem& sm = *reinterpret_cast<SpanSmem*>(smem_raw);

    const int tid  = threadIdx.x;
    const int warp = tid >> 5;
    const int lane = tid & 31;
    const int g    = lane >> 2;
    const int tq   = lane & 3;
    const int m0 = blockIdx.x * 64;
    const int NCK = NHEAD * KTAPS;   // 54

    // load full Wck into smem (tf32)
    for (int i = tid; i < 384 * NCK; i += 128)
        sm.Bw[i / NCK][i % NCK] = f2t(Wck[i]);

    float acc[8][4];
#pragma unroll
    for (int nc = 0; nc < 8; nc++)
#pragma unroll
        for (int i = 0; i < 4; i++) acc[nc][i] = 0.f;

    const int a_k4 = (tid & 7) * 4;
    const int a_rb = tid >> 3;

    float4 xr[4], qr[4];
#pragma unroll
    for (int p = 0; p < 4; p++) {
        const size_t off = (size_t)(m0 + a_rb + 16 * p) * AHS + a_k4;
        xr[p] = *(const float4*)(kc + off);
        qr[p] = *(const float4*)(q + off);
    }

    for (int k0 = 0; k0 < AHS; k0 += 32) {
#pragma unroll
        for (int p = 0; p < 4; p++) {
            const int row = a_rb + 16 * p;
            sm.As[a_k4 + 0][row] = f2t(xr[p].x * qr[p].x);
            sm.As[a_k4 + 1][row] = f2t(xr[p].y * qr[p].y);
            sm.As[a_k4 + 2][row] = f2t(xr[p].z * qr[p].z);
            sm.As[a_k4 + 3][row] = f2t(xr[p].w * qr[p].w);
        }
        __syncthreads();

        if (k0 + 32 < AHS) {
#pragma unroll
            for (int p = 0; p < 4; p++) {
                const size_t off = (size_t)(m0 + a_rb + 16 * p) * AHS + k0 + 32 + a_k4;
                xr[p] = *(const float4*)(kc + off);
                qr[p] = *(const float4*)(q + off);
            }
        }

#pragma unroll
        for (int kk = 0; kk < 4; kk++) {
            unsigned a[4];
            a[0] = sm.As[kk * 8 + tq    ][warp * 16 + g    ];
            a[1] = sm.As[kk * 8 + tq    ][warp * 16 + g + 8];
            a[2] = sm.As[kk * 8 + tq + 4][warp * 16 + g    ];
            a[3] = sm.As[kk * 8 + tq + 4][warp * 16 + g + 8];
#pragma unroll
            for (int nc = 0; nc < 7; nc++) {   // cols 0..55 cover the 54 valid
                unsigned b[2];
                b[0] = sm.Bw[k0 + kk * 8 + tq    ][nc * 8 + g];
                b[1] = sm.Bw[k0 + kk * 8 + tq + 4][nc * 8 + g];
                mma_tf32(acc[nc], a, b);
            }
        }
        __syncthreads();
    }

    const int r0 = m0 + warp * 16 + g;
#pragma unroll
    for (int nc = 0; nc < 7; nc++) {
        const int col = nc * 8 + 2 * tq;
        if (col < NCK) {
            const float bv0 = bck[col], bv1 = bck[col + 1];
            ck[(size_t)r0 * 64 + col]           = acc[nc][0] + bv0;
            ck[(size_t)r0 * 64 + col + 1]       = acc[nc][1] + bv1;
            ck[(size_t)(r0 + 8) * 64 + col]     = acc[nc][2] + bv0;
            ck[(size_t)(r0 + 8) * 64 + col + 1] = acc[nc][3] + bv1;
        }
    }
}

// ---------------- softmax + dynamic conv (smem tiled) ----------------------
struct DynSmem {
    float cot[40][384];
    float p[32][56];
};

__global__ __launch_bounds__(384)
void dynsoft2(const float* __restrict__ ckraw, const float* __restrict__ co,
              float* __restrict__ out)
{
    extern __shared__ char smem_raw[];
    DynSmem& sm = *reinterpret_cast<DynSmem*>(smem_raw);
    const int tid = threadIdx.x;
    const int row0 = blockIdx.x * 32;
    const int b = row0 >> 11;
    const int s0 = row0 & (SEQ - 1);

    for (int j = 0; j < 40; j++) {
        const int ss = s0 + j - 4;
        sm.cot[j][tid] = (ss >= 0 && ss < SEQ)
            ? co[(size_t)(b * SEQ + ss) * AHS + tid] : 0.f;
    }
    if (tid < 32 * NHEAD) {
        const int r = tid / NHEAD, h = tid % NHEAD;
        const float* lr = ckraw + (size_t)(row0 + r) * 64 + h * KTAPS;
        float m = -1e30f;
#pragma unroll
        for (int t = 0; t < KTAPS; t++) m = fmaxf(m, lr[t]);
        float e[KTAPS], s = 0.f;
#pragma unroll
        for (int t = 0; t < KTAPS; t++) { e[t] = __expf(lr[t] - m); s += e[t]; }
        const float inv = 1.f / s;
#pragma unroll
        for (int t = 0; t < KTAPS; t++) sm.p[r][h * KTAPS + t] = e[t] * inv;
    }
    __syncthreads();

    const int h = tid >> 6;
#pragma unroll 4
    for (int si = 0; si < 32; si++) {
        float acc = 0.f;
#pragma unroll
        for (int t = 0; t < KTAPS; t++)
            acc = fmaf(sm.p[si][h * KTAPS + t], sm.cot[si + t][tid], acc);
        out[(size_t)(row0 + si) * (2 * AHS) + AHS + tid] = acc;
    }
}

// ---------------- flash attention (tf32 mma, cp.async pipelined) -----------
// BQ=128 (8 warps x 16 rows), BK=64, double-buffered K/V, per-warp P staging.
struct AttnSmem {
    unsigned Ks[2][64][72];
    unsigned Vs[2][64][72];
    unsigned Ss[8][16][36];   // per-warp P staging (32-key half at a time)
};

__global__ __launch_bounds__(256, 2)
void attn_tf32(const float* __restrict__ q, const unsigned* __restrict__ kt,
               const unsigned* __restrict__ vt, const float* __restrict__ mask,
               const float* __restrict__ headmask, float* __restrict__ out)
{
    extern __shared__ char smem_raw[];
    AttnSmem& sm = *reinterpret_cast<AttnSmem*>(smem_raw);

    const int tid  = threadIdx.x;
    const int warp = tid >> 5;
    const int lane = tid & 31;
    const int g    = lane >> 2;
    const int tq   = lane & 3;

    const int bh = blockIdx.y;
    const int b = bh / NHEAD, h = bh % NHEAD;
    const int q0 = blockIdx.x * 128;

    // Q fragments (pre-scaled, tf32)
    unsigned aq[8][4];
    {
        const float* qp = q + (size_t)(b * SEQ + q0 + warp * 16) * AHS + h * HDIM;
#pragma unroll
        for (int kc = 0; kc < 8; kc++) {
            aq[kc][0] = f2t(qp[(size_t)g       * AHS + kc * 8 + tq    ] * 0.125f);
            aq[kc][1] = f2t(qp[(size_t)(g + 8) * AHS + kc * 8 + tq    ] * 0.125f);
            aq[kc][2] = f2t(qp[(size_t)g       * AHS + kc * 8 + tq + 4] * 0.125f);
            aq[kc][3] = f2t(qp[(size_t)(g + 8) * AHS + kc * 8 + tq + 4] * 0.125f);
        }
    }

    float o[8][4];
#pragma unroll
    for (int nc = 0; nc < 8; nc++)
#pragma unroll
        for (int i = 0; i < 4; i++) o[nc][i] = 0.f;
    float mrun0 = -1e30f, mrun1 = -1e30f, l0 = 0.f, l1 = 0.f;

    const int lrow = tid >> 2;
    const int lseg = (tid & 3) * 16;
    const unsigned* kbase = kt + (size_t)b * SEQ * AHS + h * HDIM;
    const unsigned* vbase = vt + (size_t)b * SEQ * AHS + h * HDIM;
    const float* mbase = mask + (size_t)b * SEQ;

#define ISSUE_KV(ibufv, kbv) do {                                             \
        const unsigned* kr_ = kbase + (size_t)((kbv) + lrow) * AHS + lseg;     \
        const unsigned* vr_ = vbase + (size_t)((kbv) + lrow) * AHS + lseg;     \
        _Pragma("unroll")                                                      \
        for (int f_ = 0; f_ < 4; f_++) {                                       \
            cpa16(&sm.Ks[ibufv][lrow][lseg + f_ * 4], kr_ + f_ * 4);           \
            cpa16(&sm.Vs[ibufv][lrow][lseg + f_ * 4], vr_ + f_ * 4);           \
        }                                                                      \
        asm volatile("cp.async.commit_group;");                                \
    } while (0)

    ISSUE_KV(0, 0);

    for (int kb = 0; kb < SEQ; kb += 64) {
        asm volatile("cp.async.wait_group 0;");
        __syncthreads();
        const int ibuf = (kb >> 6) & 1;
        if (kb + 64 < SEQ) ISSUE_KV(ibuf ^ 1, kb + 64);

        // mask values (L2 hits, issued early)
        float mv0[8], mv1[8];
#pragma unroll
        for (int nc = 0; nc < 8; nc++) {
            mv0[nc] = __ldg(mbase + kb + nc * 8 + 2 * tq);
            mv1[nc] = __ldg(mbase + kb + nc * 8 + 2 * tq + 1);
        }

        // ---- scores ----
        float sfr[8][4];
#pragma unroll
        for (int nc = 0; nc < 8; nc++) {
            sfr[nc][0] = sfr[nc][1] = sfr[nc][2] = sfr[nc][3] = 0.f;
#pragma unroll
            for (int kc = 0; kc < 8; kc++) {
                uint2 bb = *(const uint2*)&sm.Ks[ibuf][nc * 8 + g][kc * 8 + 2 * tq];
                mma_tf32(sfr[nc], aq[kc], (const unsigned*)&bb);
            }
            sfr[nc][0] += mv0[nc]; sfr[nc][1] += mv1[nc];
            sfr[nc][2] += mv0[nc]; sfr[nc][3] += mv1[nc];
        }

        // ---- online softmax stats ----
        float rmax0 = -1e30f, rmax1 = -1e30f;
#pragma unroll
        for (int nc = 0; nc < 8; nc++) {
            rmax0 = fmaxf(rmax0, fmaxf(sfr[nc][0], sfr[nc][1]));
            rmax1 = fmaxf(rmax1, fmaxf(sfr[nc][2], sfr[nc][3]));
        }
        rmax0 = fmaxf(rmax0, __shfl_xor_sync(0xffffffffu, rmax0, 1));
        rmax0 = fmaxf(rmax0, __shfl_xor_sync(0xffffffffu, rmax0, 2));
        rmax1 = fmaxf(rmax1, __shfl_xor_sync(0xffffffffu, rmax1, 1));
        rmax1 = fmaxf(rmax1, __shfl_xor_sync(0xffffffffu, rmax1, 2));

        const float nm0 = fmaxf(mrun0, rmax0);
        const float nm1 = fmaxf(mrun1, rmax1);
        const float corr0 = __expf(mrun0 - nm0);
        const float corr1 = __expf(mrun1 - nm1);
        l0 *= corr0; l1 *= corr1;
#pragma unroll
        for (int nc = 0; nc < 8; nc++) {
            o[nc][0] *= corr0; o[nc][1] *= corr0;
            o[nc][2] *= corr1; o[nc][3] *= corr1;
        }
        mrun0 = nm0; mrun1 = nm1;

        float rsum0 = 0.f, rsum1 = 0.f;
#pragma unroll
        for (int half = 0; half < 2; half++) {
#pragma unroll
            for (int nn = 0; nn < 4; nn++) {
                const int nc = half * 4 + nn;
                float p0 = __expf(sfr[nc][0] - nm0);
                float p1 = __expf(sfr[nc][1] - nm0);
                float p2 = __expf(sfr[nc][2] - nm1);
                float p3 = __expf(sfr[nc][3] - nm1);
                rsum0 += p0 + p1;
                rsum1 += p2 + p3;
                *(uint2*)&sm.Ss[warp][g    ][nn * 8 + 2 * tq] = make_uint2(f2t(p0), f2t(p1));
                *(uint2*)&sm.Ss[warp][g + 8][nn * 8 + 2 * tq] = make_uint2(f2t(p2), f2t(p3));
            }
            __syncwarp();
#pragma unroll
            for (int kc = 0; kc < 4; kc++) {
                unsigned ap[4];
                ap[0] = sm.Ss[warp][g    ][kc * 8 + tq    ];
                ap[1] = sm.Ss[warp][g + 8][kc * 8 + tq    ];
                ap[2] = sm.Ss[warp][g    ][kc * 8 + tq + 4];
                ap[3] = sm.Ss[warp][g + 8][kc * 8 + tq + 4];
#pragma unroll
                for (int nd = 0; nd < 8; nd++) {
                    unsigned bfr[2];
                    bfr[0] = sm.Vs[ibuf][half * 32 + kc * 8 + tq    ][nd * 8 + g];
                    bfr[1] = sm.Vs[ibuf][half * 32 + kc * 8 + tq + 4][nd * 8 + g];
                    mma_tf32(o[nd], ap, bfr);
                }
            }
            __syncwarp();
        }
        rsum0 += __shfl_xor_sync(0xffffffffu, rsum0, 1);
        rsum0 += __shfl_xor_sync(0xffffffffu, rsum0, 2);
        rsum1 += __shfl_xor_sync(0xffffffffu, rsum1, 1);
        rsum1 += __shfl_xor_sync(0xffffffffu, rsum1, 2);
        l0 += rsum0; l1 += rsum1;
    }
#undef ISSUE_KV

    const float hm = headmask[h];
    const float inv0 = hm / l0;
    const float inv1 = hm / l1;
    const int r0 = b * SEQ + q0 + warp * 16 + g;
#pragma unroll
    for (int nd = 0; nd < 8; nd++) {
        const int col = h * HDIM + nd * 8 + 2 * tq;
        *(float2*)(out + (size_t)r0 * (2 * AHS) + col) =
            make_float2(o[nd][0] * inv0, o[nd][1] * inv0);
        *(float2*)(out + (size_t)(r0 + 8) * (2 * AHS) + col) =
            make_float2(o[nd][2] * inv1, o[nd][3] * inv1);
    }
}

// ---------------------------------------------------------------------------
extern "C" void kernel_launch(void* const* d_in, const int* in_sizes, int n_in,
                              void* d_out, int out_size)
{
    const float* hs    = (const float*)d_in[0];
    const float* amask = (const float*)d_in[1];
    const float* hmask = (const float*)d_in[2];
    const float* Wq    = (const float*)d_in[3];
    const float* bq    = (const float*)d_in[4];
    const float* Wk    = (const float*)d_in[5];
    const float* bk    = (const float*)d_in[6];
    const float* Wv    = (const float*)d_in[7];
    const float* bv    = (const float*)d_in[8];
    const float* dwk   = (const float*)d_in[9];
    const float* pw    = (const float*)d_in[10];
    const float* cb    = (const float*)d_in[11];
    const float* Wck   = (const float*)d_in[12];
    const float* bck   = (const float*)d_in[13];
    const float* Wco   = (const float*)d_in[14];
    const float* bco   = (const float*)d_in[15];
    float* out = (float*)d_out;

    float *pq, *pco, *pkc, *pdw, *pck;
    unsigned *pkt, *pvt;
    cudaGetSymbolAddress((void**)&pq,  g_q);
    cudaGetSymbolAddress((void**)&pkt, g_kt);
    cudaGetSymbolAddress((void**)&pvt, g_vt);
    cudaGetSymbolAddress((void**)&pco, g_co);
    cudaGetSymbolAddress((void**)&pkc, g_kc);
    cudaGetSymbolAddress((void**)&pdw, g_dw);
    cudaGetSymbolAddress((void**)&pck, g_ck);

    cudaFuncSetAttribute(attn_tf32, cudaFuncAttributeMaxDynamicSharedMemorySize,
                         (int)sizeof(AttnSmem));
    cudaFuncSetAttribute(span_gemm, cudaFuncAttributeMaxDynamicSharedMemorySize,
                         (int)sizeof(SpanSmem));
    cudaFuncSetAttribute(dynsoft2, cudaFuncAttributeMaxDynamicSharedMemorySize,
                         (int)sizeof(DynSmem));

    // 1: fused Q/K/V/CO projections
    gemm4_tf32<<<dim3(AHS / 64, MROWS / 64, 4), 128>>>(
        hs, Wq, Wk, Wv, Wco, bq, bk, bv, bco, pq, pkt, pvt, pco);

    // 2: depthwise conv (smem tiled)
    dwconv9s<<<dim3(CIN / 256, MROWS / 32), 256>>>(hs, dwk, pdw);

    // 3: pointwise projection (z=0 float path -> pkc)
    gemm4_tf32<<<dim3(AHS / 64, MROWS / 64, 1), 128>>>(
        pdw, pw, pw, pw, pw, cb, cb, cb, cb, pkc, pkt, pvt, pco);

    // 4: span logits GEMM (persistent Wck)
    span_gemm<<<MROWS / 64, 128, sizeof(SpanSmem)>>>(pkc, pq, Wck, bck, pck);

    // 5: softmax + dynamic conv
    dynsoft2<<<MROWS / 32, 384, sizeof(DynSmem)>>>(pck, pco, out);

    // 6: flash attention (profiled slot)
    attn_tf32<<<dim3(SEQ / 128, BATCH * NHEAD), 256, sizeof(AttnSmem)>>>(
        pq, pkt, pvt, amask, hmask, out);
}

// round 6
// speedup vs baseline: 6.6243x; 1.9507x over previous
#include <cuda_runtime.h>
#include <cuda_fp16.h>

// ---------------------------------------------------------------------------
// TFConvBertSelfAttention  (B=4, S=2048, C=768, H=6, D=64, AHS=384, K=9)
// R6 (=R5 fixed): fp16 m16n8k16 everywhere GEMM-shaped. K half2-packed along
// dim; V transposed pair-packed in producer epilogue. fp32 accum + softmax.
// ---------------------------------------------------------------------------

#define BATCH   4
#define SEQ     2048
#define CIN     768
#define NHEAD   6
#define HDIM    64
#define AHS     384
#define KTAPS   9
#define MROWS   (BATCH * SEQ)          // 8192

// ------------------------- scratch (static device mem) ---------------------
__device__ float    g_q [MROWS * AHS];
__device__ unsigned g_kt[MROWS * (AHS / 2)];        // half2 along dim, [tok][192]
__device__ unsigned g_vtT[AHS * (MROWS / 2)];       // half2 along token, [col][4096]
__device__ float    g_co[MROWS * AHS];
__device__ float    g_kc[MROWS * AHS];
__device__ float    g_dw[MROWS * CIN];
__device__ float    g_ck[MROWS * 64];               // span logits (54 valid)

// ------------------------- helpers -----------------------------------------
__device__ __forceinline__ unsigned f2h2(float lo, float hi) {
    unsigned r;
    asm("cvt.rn.f16x2.f32 %0, %1, %2;" : "=r"(r) : "f"(hi), "f"(lo));
    return r;
}

__device__ __forceinline__ void mma_f16(float* c, const unsigned* a,
                                        unsigned b0, unsigned b1) {
    asm volatile(
        "mma.sync.aligned.m16n8k16.row.col.f32.f16.f16.f32 "
        "{%0,%1,%2,%3}, {%4,%5,%6,%7}, {%8,%9}, {%0,%1,%2,%3};\n"
        : "+f"(c[0]), "+f"(c[1]), "+f"(c[2]), "+f"(c[3])
        : "r"(a[0]), "r"(a[1]), "r"(a[2]), "r"(a[3]), "r"(b0), "r"(b1));
}

__device__ __forceinline__ void cpa16(void* sm, const void* g) {
    unsigned sa = (unsigned)__cvta_generic_to_shared(sm);
    asm volatile("cp.async.cg.shared.global [%0], [%1], 16;" :: "r"(sa), "l"(g));
}

// ------------------------- fp16 GEMM, grid.z selects weight set -------------
// z=0: float out (+bias)  z=1: k -> g_kt (half2 dim pairs)
// z=2: v -> g_vtT (half2 token pairs, transposed)  z=3: co (float+bias)
__global__ __launch_bounds__(128)
void gemm4_f16(const float* __restrict__ A,
               const float* __restrict__ W0, const float* __restrict__ W1,
               const float* __restrict__ W2, const float* __restrict__ W3,
               const float* __restrict__ b0, const float* __restrict__ b1,
               const float* __restrict__ b2, const float* __restrict__ b3,
               float* __restrict__ Oq, unsigned* __restrict__ Okt,
               unsigned* __restrict__ OvtT, float* __restrict__ Oco)
{
    const float* Ws[4] = {W0, W1, W2, W3};
    const float* bs[4] = {b0, b1, b2, b3};
    const int z = blockIdx.z;
    const float* B = Ws[z];
    const float* bias = bs[z];

    __shared__ unsigned Ash[64][20];   // [m][kpair], 16 pairs + 4 pad
    __shared__ unsigned Bsh[16][72];   // [kpair][n], 64 cols + 8 pad

    const int tid  = threadIdx.x;
    const int warp = tid >> 5;
    const int lane = tid & 31;
    const int g    = lane >> 2;
    const int tq   = lane & 3;
    const int m0 = blockIdx.y * 64;
    const int n0 = blockIdx.x * 64;

    float acc[8][4];
#pragma unroll
    for (int nc = 0; nc < 8; nc++)
#pragma unroll
        for (int i = 0; i < 4; i++) acc[nc][i] = 0.f;

    const int a_k4 = (tid & 7) * 4;    // k offset 0..28
    const int a_rb = tid >> 3;         // 0..15
    const int b_kp = tid >> 4;         // 0..7
    const int b_c4 = (tid & 15) * 4;   // 0..60

    float4 ar[4];
    float4 br[2][2];
#pragma unroll
    for (int p = 0; p < 4; p++)
        ar[p] = *(const float4*)(A + (size_t)(m0 + a_rb + 16 * p) * CIN + a_k4);
#pragma unroll
    for (int p = 0; p < 2; p++) {
        const int kp = b_kp + 8 * p;
        br[p][0] = *(const float4*)(B + (size_t)(2 * kp)     * AHS + n0 + b_c4);
        br[p][1] = *(const float4*)(B + (size_t)(2 * kp + 1) * AHS + n0 + b_c4);
    }

    for (int k0 = 0; k0 < CIN; k0 += 32) {
#pragma unroll
        for (int p = 0; p < 4; p++) {
            const int row = a_rb + 16 * p;
            Ash[row][a_k4 / 2]     = f2h2(ar[p].x, ar[p].y);
            Ash[row][a_k4 / 2 + 1] = f2h2(ar[p].z, ar[p].w);
        }
#pragma unroll
        for (int p = 0; p < 2; p++) {
            const int kp = b_kp + 8 * p;
            Bsh[kp][b_c4 + 0] = f2h2(br[p][0].x, br[p][1].x);
            Bsh[kp][b_c4 + 1] = f2h2(br[p][0].y, br[p][1].y);
            Bsh[kp][b_c4 + 2] = f2h2(br[p][0].z, br[p][1].z);
            Bsh[kp][b_c4 + 3] = f2h2(br[p][0].w, br[p][1].w);
        }
        __syncthreads();

        if (k0 + 32 < CIN) {
#pragma unroll
            for (int p = 0; p < 4; p++)
                ar[p] = *(const float4*)(A + (size_t)(m0 + a_rb + 16 * p) * CIN + k0 + 32 + a_k4);
#pragma unroll
            for (int p = 0; p < 2; p++) {
                const int kp = b_kp + 8 * p;
                br[p][0] = *(const float4*)(B + (size_t)(k0 + 32 + 2 * kp)     * AHS + n0 + b_c4);
                br[p][1] = *(const float4*)(B + (size_t)(k0 + 32 + 2 * kp + 1) * AHS + n0 + b_c4);
            }
        }

#pragma unroll
        for (int kcc = 0; kcc < 2; kcc++) {
            unsigned a[4];
            a[0] = Ash[warp * 16 + g    ][kcc * 8 + tq    ];
            a[1] = Ash[warp * 16 + g + 8][kcc * 8 + tq    ];
            a[2] = Ash[warp * 16 + g    ][kcc * 8 + tq + 4];
            a[3] = Ash[warp * 16 + g + 8][kcc * 8 + tq + 4];
#pragma unroll
            for (int nc = 0; nc < 8; nc++)
                mma_f16(acc[nc], a,
                        Bsh[kcc * 8 + tq    ][nc * 8 + g],
                        Bsh[kcc * 8 + tq + 4][nc * 8 + g]);
        }
        __syncthreads();
    }

    const int r0 = m0 + warp * 16 + g;
    if (z == 0 || z == 3) {
        float* C = (z == 0) ? Oq : Oco;
#pragma unroll
        for (int nc = 0; nc < 8; nc++) {
            const int col = n0 + nc * 8 + 2 * tq;
            const float bv0 = bias[col], bv1 = bias[col + 1];
            *(float2*)(C + (size_t)r0 * AHS + col) =
                make_float2(acc[nc][0] + bv0, acc[nc][1] + bv1);
            *(float2*)(C + (size_t)(r0 + 8) * AHS + col) =
                make_float2(acc[nc][2] + bv0, acc[nc][3] + bv1);
        }
    } else if (z == 1) {
        // K: half2 pairs along dim, layout [token][AHS/2]
#pragma unroll
        for (int nc = 0; nc < 8; nc++) {
            const int col = n0 + nc * 8 + 2 * tq;
            const float bv0 = bias[col], bv1 = bias[col + 1];
            const int cp = col >> 1;   // col is even
            Okt[(size_t)r0 * (AHS / 2) + cp]       = f2h2(acc[nc][0] + bv0, acc[nc][1] + bv1);
            Okt[(size_t)(r0 + 8) * (AHS / 2) + cp] = f2h2(acc[nc][2] + bv0, acc[nc][3] + bv1);
        }
    } else {
        // V: transposed, half2 pairs along token, layout [col][MROWS/2]
        // Row pairs: rows r0 (g) and partner row from lane^4 (g^1).
#pragma unroll
        for (int nc = 0; nc < 8; nc++) {
            const int col = n0 + nc * 8 + 2 * tq;
            const float bv0 = bias[col], bv1 = bias[col + 1];
            const unsigned ulo = f2h2(acc[nc][0] + bv0, acc[nc][1] + bv1);  // row r0
            const unsigned uhi = f2h2(acc[nc][2] + bv0, acc[nc][3] + bv1);  // row r0+8
            const unsigned plo = __shfl_xor_sync(0xffffffffu, ulo, 4);      // partner row r0^1
            const unsigned phi = __shfl_xor_sync(0xffffffffu, uhi, 4);
            unsigned w0, w1;
            size_t gp;
            if ((g & 1) == 0) {
                // owns even row 2m: pack (row 2m, row 2m+1) for rows r0,r0+1
                w0 = (ulo & 0xFFFFu) | (plo << 16);          // col   : (r0, r0+1)
                w1 = (ulo >> 16)     | (plo & 0xFFFF0000u);  // col+1 : (r0, r0+1)
                gp = (size_t)(r0 >> 1);
                OvtT[(size_t)col * (MROWS / 2) + gp]       = w0;
                OvtT[(size_t)(col + 1) * (MROWS / 2) + gp] = w1;
                // rows r0+8, r0+9 -> handled by partner's odd branch? No:
                // rows 8..15 pair as (8,9),(10,11)... same parity logic, use uhi/phi
                w0 = (uhi & 0xFFFFu) | (phi << 16);
                w1 = (uhi >> 16)     | (phi & 0xFFFF0000u);
                gp = (size_t)((r0 + 8) >> 1);
                OvtT[(size_t)col * (MROWS / 2) + gp]       = w0;
                OvtT[(size_t)(col + 1) * (MROWS / 2) + gp] = w1;
            }
        }
    }
}

// ------------------------- depthwise conv, smem tiled ----------------------
__global__ __launch_bounds__(256)
void dwconv9s(const float* __restrict__ hs, const float* __restrict__ w,
              float* __restrict__ out)
{
    __shared__ float tile[40][256];
    const int tid = threadIdx.x;
    const int c0  = blockIdx.x * 256;
    const int row0 = blockIdx.y * 32;
    const int b = row0 >> 11;
    const int s0 = row0 & (SEQ - 1);

    for (int i = tid; i < 40 * 256; i += 256) {
        const int r = i >> 8, c = i & 255;
        const int ss = s0 + r - 4;
        tile[r][c] = (ss >= 0 && ss < SEQ)
            ? hs[(size_t)(b * SEQ + ss) * CIN + c0 + c] : 0.f;
    }
    float wr[KTAPS];
#pragma unroll
    for (int t = 0; t < KTAPS; t++) wr[t] = w[t * CIN + c0 + tid];
    __syncthreads();

#pragma unroll 4
    for (int si = 0; si < 32; si++) {
        float acc = 0.f;
#pragma unroll
        for (int t = 0; t < KTAPS; t++)
            acc = fmaf(tile[si + t][tid], wr[t], acc);
        out[(size_t)(row0 + si) * CIN + c0 + tid] = acc;
    }
}

// ---------------- span GEMM: logits = (kc*q) @ Wck + bck -------------------
struct SpanSmem {
    unsigned As[64][20];     // [m][kpair of 32-k tile]
    unsigned Bw[192][56];    // [global kpair][col], 54 valid cols
};

__global__ __launch_bounds__(128)
void span_gemm(const float* __restrict__ kcv, const float* __restrict__ q,
               const float* __restrict__ Wck, const float* __restrict__ bck,
               float* __restrict__ ck)
{
    extern __shared__ char smem_raw[];
    SpanSmem& sm = *reinterpret_cast<SpanSmem*>(smem_raw);

    const int tid  = threadIdx.x;
    const int warp = tid >> 5;
    const int lane = tid & 31;
    const int g    = lane >> 2;
    const int tq   = lane & 3;
    const int m0 = blockIdx.x * 64;
    const int NCK = NHEAD * KTAPS;   // 54

    for (int idx = tid; idx < 192 * NCK; idx += 128) {
        const int kp = idx / NCK, c = idx % NCK;
        sm.Bw[kp][c] = f2h2(Wck[(size_t)(2 * kp) * NCK + c],
                            Wck[(size_t)(2 * kp + 1) * NCK + c]);
    }
    for (int idx = tid; idx < 192 * 2; idx += 128)
        sm.Bw[idx >> 1][54 + (idx & 1)] = 0u;

    float acc[7][4];
#pragma unroll
    for (int nc = 0; nc < 7; nc++)
#pragma unroll
        for (int i = 0; i < 4; i++) acc[nc][i] = 0.f;

    const int a_k4 = (tid & 7) * 4;
    const int a_rb = tid >> 3;

    float4 xr[4], qr[4];
#pragma unroll
    for (int p = 0; p < 4; p++) {
        const size_t off = (size_t)(m0 + a_rb + 16 * p) * AHS + a_k4;
        xr[p] = *(const float4*)(kcv + off);
        qr[p] = *(const float4*)(q + off);
    }

    for (int k0 = 0; k0 < AHS; k0 += 32) {
#pragma unroll
        for (int p = 0; p < 4; p++) {
            const int row = a_rb + 16 * p;
            sm.As[row][a_k4 / 2]     = f2h2(xr[p].x * qr[p].x, xr[p].y * qr[p].y);
            sm.As[row][a_k4 / 2 + 1] = f2h2(xr[p].z * qr[p].z, xr[p].w * qr[p].w);
        }
        __syncthreads();

        if (k0 + 32 < AHS) {
#pragma unroll
            for (int p = 0; p < 4; p++) {
                const size_t off = (size_t)(m0 + a_rb + 16 * p) * AHS + k0 + 32 + a_k4;
                xr[p] = *(const float4*)(kcv + off);
                qr[p] = *(const float4*)(q + off);
            }
        }

#pragma unroll
        for (int kcc = 0; kcc < 2; kcc++) {
            unsigned a[4];
            a[0] = sm.As[warp * 16 + g    ][kcc * 8 + tq    ];
            a[1] = sm.As[warp * 16 + g + 8][kcc * 8 + tq    ];
            a[2] = sm.As[warp * 16 + g    ][kcc * 8 + tq + 4];
            a[3] = sm.As[warp * 16 + g + 8][kcc * 8 + tq + 4];
            const int kpb = k0 / 2 + kcc * 8;
#pragma unroll
            for (int nc = 0; nc < 7; nc++)
                mma_f16(acc[nc], a,
                        sm.Bw[kpb + tq    ][nc * 8 + g],
                        sm.Bw[kpb + tq + 4][nc * 8 + g]);
        }
        __syncthreads();
    }

    const int r0 = m0 + warp * 16 + g;
#pragma unroll
    for (int nc = 0; nc < 7; nc++) {
        const int col = nc * 8 + 2 * tq;
        if (col < NCK) {
            const float bv0 = bck[col], bv1 = bck[col + 1];
            ck[(size_t)r0 * 64 + col]           = acc[nc][0] + bv0;
            ck[(size_t)r0 * 64 + col + 1]       = acc[nc][1] + bv1;
            ck[(size_t)(r0 + 8) * 64 + col]     = acc[nc][2] + bv0;
            ck[(size_t)(r0 + 8) * 64 + col + 1] = acc[nc][3] + bv1;
        }
    }
}

// ---------------- softmax + dynamic conv (smem tiled) ----------------------
struct DynSmem {
    float cot[40][384];
    float p[32][56];
};

__global__ __launch_bounds__(384)
void dynsoft2(const float* __restrict__ ckraw, const float* __restrict__ co,
              float* __restrict__ out)
{
    extern __shared__ char smem_raw[];
    DynSmem& sm = *reinterpret_cast<DynSmem*>(smem_raw);
    const int tid = threadIdx.x;
    const int row0 = blockIdx.x * 32;
    const int b = row0 >> 11;
    const int s0 = row0 & (SEQ - 1);

    for (int j = 0; j < 40; j++) {
        const int ss = s0 + j - 4;
        sm.cot[j][tid] = (ss >= 0 && ss < SEQ)
            ? co[(size_t)(b * SEQ + ss) * AHS + tid] : 0.f;
    }
    if (tid < 32 * NHEAD) {
        const int r = tid / NHEAD, h = tid % NHEAD;
        const float* lr = ckraw + (size_t)(row0 + r) * 64 + h * KTAPS;
        float m = -1e30f;
#pragma unroll
        for (int t = 0; t < KTAPS; t++) m = fmaxf(m, lr[t]);
        float e[KTAPS], s = 0.f;
#pragma unroll
        for (int t = 0; t < KTAPS; t++) { e[t] = __expf(lr[t] - m); s += e[t]; }
        const float inv = 1.f / s;
#pragma unroll
        for (int t = 0; t < KTAPS; t++) sm.p[r][h * KTAPS + t] = e[t] * inv;
    }
    __syncthreads();

    const int h = tid >> 6;
#pragma unroll 4
    for (int si = 0; si < 32; si++) {
        float acc = 0.f;
#pragma unroll
        for (int t = 0; t < KTAPS; t++)
            acc = fmaf(sm.p[si][h * KTAPS + t], sm.cot[si + t][tid], acc);
        out[(size_t)(row0 + si) * (2 * AHS) + AHS + tid] = acc;
    }
}

// ---------------- flash attention (fp16 mma) -> out[:, 0:384] --------------
// BQ=128 (8 warps), BK=64, cp.async double buffer, 2 blocks/SM.
struct AttnSmem {
    unsigned Ks[2][64][36];   // [tok][dim pair], 32 + 4 pad
    unsigned Vs[2][64][36];   // [dim][tok pair], 32 + 4 pad
    unsigned Ss[8][16][36];   // per-warp P fp16 pairs
};

__global__ __launch_bounds__(256, 2)
void attn_f16(const float* __restrict__ q, const unsigned* __restrict__ kt,
              const unsigned* __restrict__ vtT, const float* __restrict__ mask,
              const float* __restrict__ headmask, float* __restrict__ out)
{
    extern __shared__ char smem_raw[];
    AttnSmem& sm = *reinterpret_cast<AttnSmem*>(smem_raw);

    const int tid  = threadIdx.x;
    const int warp = tid >> 5;
    const int lane = tid & 31;
    const int g    = lane >> 2;
    const int tq   = lane & 3;

    const int bh = blockIdx.y;
    const int b = bh / NHEAD, h = bh % NHEAD;
    const int q0 = blockIdx.x * 128;
    const int bS = b * SEQ;

    // Q fragments (pre-scaled, fp16 packed)
    unsigned aq[4][4];
    {
        const float* qp = q + (size_t)(bS + q0 + warp * 16) * AHS + h * HDIM;
        const float s = 0.125f;
#pragma unroll
        for (int kc = 0; kc < 4; kc++) {
            const int c0 = kc * 16 + 2 * tq;
            aq[kc][0] = f2h2(qp[(size_t)g       * AHS + c0]     * s, qp[(size_t)g       * AHS + c0 + 1] * s);
            aq[kc][1] = f2h2(qp[(size_t)(g + 8) * AHS + c0]     * s, qp[(size_t)(g + 8) * AHS + c0 + 1] * s);
            aq[kc][2] = f2h2(qp[(size_t)g       * AHS + c0 + 8] * s, qp[(size_t)g       * AHS + c0 + 9] * s);
            aq[kc][3] = f2h2(qp[(size_t)(g + 8) * AHS + c0 + 8] * s, qp[(size_t)(g + 8) * AHS + c0 + 9] * s);
        }
    }

    float o[8][4];
#pragma unroll
    for (int nc = 0; nc < 8; nc++)
#pragma unroll
        for (int i = 0; i < 4; i++) o[nc][i] = 0.f;
    float mrun0 = -1e30f, mrun1 = -1e30f, l0 = 0.f, l1 = 0.f;

    const float* mbase = mask + (size_t)bS;

#define ISSUE_KV(ibv, kbv) do {                                                  \
        _Pragma("unroll")                                                        \
        for (int cc = 0; cc < 2; cc++) {                                         \
            const int ch = tid + cc * 256;                                       \
            const int rr = ch >> 3, seg = (ch & 7) * 4;                          \
            cpa16(&sm.Ks[ibv][rr][seg],                                          \
                  kt + (size_t)(bS + (kbv) + rr) * (AHS / 2) + h * 32 + seg);    \
            cpa16(&sm.Vs[ibv][rr][seg],                                          \
                  vtT + (size_t)(h * 64 + rr) * (MROWS / 2) + (bS + (kbv)) / 2 + seg); \
        }                                                                        \
        asm volatile("cp.async.commit_group;");                                  \
    } while (0)

    ISSUE_KV(0, 0);

    for (int kb = 0; kb < SEQ; kb += 64) {
        asm volatile("cp.async.wait_group 0;");
        __syncthreads();
        const int ibuf = (kb >> 6) & 1;
        if (kb + 64 < SEQ) ISSUE_KV(ibuf ^ 1, kb + 64);

        float mv0[8], mv1[8];
#pragma unroll
        for (int nc = 0; nc < 8; nc++) {
            mv0[nc] = __ldg(mbase + kb + nc * 8 + 2 * tq);
            mv1[nc] = __ldg(mbase + kb + nc * 8 + 2 * tq + 1);
        }

        // ---- scores: S[16 x 64] ----
        float sfr[8][4];
#pragma unroll
        for (int nc = 0; nc < 8; nc++) {
            sfr[nc][0] = sfr[nc][1] = sfr[nc][2] = sfr[nc][3] = 0.f;
#pragma unroll
            for (int kc = 0; kc < 4; kc++)
                mma_f16(sfr[nc], aq[kc],
                        sm.Ks[ibuf][nc * 8 + g][kc * 8 + tq    ],
                        sm.Ks[ibuf][nc * 8 + g][kc * 8 + tq + 4]);
            sfr[nc][0] += mv0[nc]; sfr[nc][1] += mv1[nc];
            sfr[nc][2] += mv0[nc]; sfr[nc][3] += mv1[nc];
        }

        // ---- online softmax ----
        float rmax0 = -1e30f, rmax1 = -1e30f;
#pragma unroll
        for (int nc = 0; nc < 8; nc++) {
            rmax0 = fmaxf(rmax0, fmaxf(sfr[nc][0], sfr[nc][1]));
            rmax1 = fmaxf(rmax1, fmaxf(sfr[nc][2], sfr[nc][3]));
        }
        rmax0 = fmaxf(rmax0, __shfl_xor_sync(0xffffffffu, rmax0, 1));
        rmax0 = fmaxf(rmax0, __shfl_xor_sync(0xffffffffu, rmax0, 2));
        rmax1 = fmaxf(rmax1, __shfl_xor_sync(0xffffffffu, rmax1, 1));
        rmax1 = fmaxf(rmax1, __shfl_xor_sync(0xffffffffu, rmax1, 2));

        const float nm0 = fmaxf(mrun0, rmax0);
        const float nm1 = fmaxf(mrun1, rmax1);
        const float corr0 = __expf(mrun0 - nm0);
        const float corr1 = __expf(mrun1 - nm1);
        l0 *= corr0; l1 *= corr1;
#pragma unroll
        for (int nc = 0; nc < 8; nc++) {
            o[nc][0] *= corr0; o[nc][1] *= corr0;
            o[nc][2] *= corr1; o[nc][3] *= corr1;
        }
        mrun0 = nm0; mrun1 = nm1;

        float rsum0 = 0.f, rsum1 = 0.f;
#pragma unroll
        for (int nc = 0; nc < 8; nc++) {
            const float p0 = __expf(sfr[nc][0] - nm0);
            const float p1 = __expf(sfr[nc][1] - nm0);
            const float p2 = __expf(sfr[nc][2] - nm1);
            const float p3 = __expf(sfr[nc][3] - nm1);
            rsum0 += p0 + p1;
            rsum1 += p2 + p3;
            sm.Ss[warp][g    ][nc * 4 + tq] = f2h2(p0, p1);
            sm.Ss[warp][g + 8][nc * 4 + tq] = f2h2(p2, p3);
        }
        rsum0 += __shfl_xor_sync(0xffffffffu, rsum0, 1);
        rsum0 += __shfl_xor_sync(0xffffffffu, rsum0, 2);
        rsum1 += __shfl_xor_sync(0xffffffffu, rsum1, 1);
        rsum1 += __shfl_xor_sync(0xffffffffu, rsum1, 2);
        l0 += rsum0; l1 += rsum1;

        __syncwarp();

        // ---- PV: O += P[16x64] x V[64x64] ----
#pragma unroll
        for (int kc = 0; kc < 4; kc++) {
            unsigned ap[4];
            ap[0] = sm.Ss[warp][g    ][kc * 8 + tq    ];
            ap[1] = sm.Ss[warp][g + 8][kc * 8 + tq    ];
            ap[2] = sm.Ss[warp][g    ][kc * 8 + tq + 4];
            ap[3] = sm.Ss[warp][g + 8][kc * 8 + tq + 4];
#pragma unroll
            for (int nd = 0; nd < 8; nd++)
                mma_f16(o[nd], ap,
                        sm.Vs[ibuf][nd * 8 + g][kc * 8 + tq    ],
                        sm.Vs[ibuf][nd * 8 + g][kc * 8 + tq + 4]);
        }
        __syncwarp();
    }
#undef ISSUE_KV

    const float hm = headmask[h];
    const float inv0 = hm / l0;
    const float inv1 = hm / l1;
    const int r0 = bS + q0 + warp * 16 + g;
#pragma unroll
    for (int nd = 0; nd < 8; nd++) {
        const int col = h * HDIM + nd * 8 + 2 * tq;
        *(float2*)(out + (size_t)r0 * (2 * AHS) + col) =
            make_float2(o[nd][0] * inv0, o[nd][1] * inv0);
        *(float2*)(out + (size_t)(r0 + 8) * (2 * AHS) + col) =
            make_float2(o[nd][2] * inv1, o[nd][3] * inv1);
    }
}

// ---------------------------------------------------------------------------
extern "C" void kernel_launch(void* const* d_in, const int* in_sizes, int n_in,
                              void* d_out, int out_size)
{
    const float* hs    = (const float*)d_in[0];
    const float* amask = (const float*)d_in[1];
    const float* hmask = (const float*)d_in[2];
    const float* Wq    = (const float*)d_in[3];
    const float* bq    = (const float*)d_in[4];
    const float* Wk    = (const float*)d_in[5];
    const float* bk    = (const float*)d_in[6];
    const float* Wv    = (const float*)d_in[7];
    const float* bv    = (const float*)d_in[8];
    const float* dwk   = (const float*)d_in[9];
    const float* pw    = (const float*)d_in[10];
    const float* cb    = (const float*)d_in[11];
    const float* Wck   = (const float*)d_in[12];
    const float* bck   = (const float*)d_in[13];
    const float* Wco   = (const float*)d_in[14];
    const float* bco   = (const float*)d_in[15];
    float* out = (float*)d_out;

    float *pq, *pco, *pkc, *pdw, *pck;
    unsigned *pkt, *pvtT;
    cudaGetSymbolAddress((void**)&pq,   g_q);
    cudaGetSymbolAddress((void**)&pkt,  g_kt);
    cudaGetSymbolAddress((void**)&pvtT, g_vtT);
    cudaGetSymbolAddress((void**)&pco,  g_co);
    cudaGetSymbolAddress((void**)&pkc,  g_kc);
    cudaGetSymbolAddress((void**)&pdw,  g_dw);
    cudaGetSymbolAddress((void**)&pck,  g_ck);

    cudaFuncSetAttribute(attn_f16, cudaFuncAttributeMaxDynamicSharedMemorySize,
                         (int)sizeof(AttnSmem));
    cudaFuncSetAttribute(span_gemm, cudaFuncAttributeMaxDynamicSharedMemorySize,
                         (int)sizeof(SpanSmem));
    cudaFuncSetAttribute(dynsoft2, cudaFuncAttributeMaxDynamicSharedMemorySize,
                         (int)sizeof(DynSmem));

    // 1: fused Q/K/V/CO projections
    gemm4_f16<<<dim3(AHS / 64, MROWS / 64, 4), 128>>>(
        hs, Wq, Wk, Wv, Wco, bq, bk, bv, bco, pq, pkt, pvtT, pco);

    // 2: depthwise conv
    dwconv9s<<<dim3(CIN / 256, MROWS / 32), 256>>>(hs, dwk, pdw);

    // 3: pointwise projection (z=0 float path -> pkc)
    gemm4_f16<<<dim3(AHS / 64, MROWS / 64, 1), 128>>>(
        pdw, pw, pw, pw, pw, cb, cb, cb, cb, pkc, pkt, pvtT, pco);

    // 4: span logits GEMM (resident fp16 Wck)
    span_gemm<<<MROWS / 64, 128, sizeof(SpanSmem)>>>(pkc, pq, Wck, bck, pck);

    // 5: softmax + dynamic conv
    dynsoft2<<<MROWS / 32, 384, sizeof(DynSmem)>>>(pck, pco, out);

    // 6: flash attention
    attn_f16<<<dim3(SEQ / 128, BATCH * NHEAD), 256, sizeof(AttnSmem)>>>(
        pq, pkt, pvtT, amask, hmask, out);
}